// round 13
// baseline (speedup 1.0000x reference)
#include <cuda_runtime.h>
#include <cstdint>

#define NY 64
#define NU 32
#define NH 512
#define BB 128
#define LCH 32
#define PCH 64
#define KIN 544   // NH + NU
#define CH (BB * NH)
#define LDCB (LCH * NY)   // 2048
#define NB 256            // mega-kernel resident blocks

typedef unsigned long long ull;

// ---------------- device scratch ----------------
__device__ float d_A[NH * NH];
__device__ float d_Pow[8][NH * NH];          // A^2,4,8,16,32,64,128,256
__device__ float d_Cbuf[NH * LCH * NY];      // [512][2048]
__device__ float d_Gp[LCH * NU * NH];        // [1024][512]
__device__ float d_Hd[LCH * NU * NY];        // [1024][64]
__device__ float d_Sv[192 * NH];             // row j = s_j (bias chain), padded
__device__ float d_yb[128 * NY];             // rows 0..31 valid
__device__ float d_Xc[(PCH + 1) * CH];
__device__ float d_S32[PCH * CH];
__device__ float d_S64[(PCH / 2) * CH];
__device__ float d_S128[(PCH / 4) * CH];
__device__ float d_S256[(PCH / 8) * CH];
__device__ unsigned d_bar;

// ---------------- f32x2 helpers ----------------
__device__ __forceinline__ ull pk2(float x) {
    ull r;
    asm("mov.b64 %0, {%1, %1};" : "=l"(r) : "f"(x));
    return r;
}
__device__ __forceinline__ void fma2(ull& d, ull a, ull b) {
    asm("fma.rn.f32x2 %0, %1, %2, %0;" : "+l"(d) : "l"(a), "l"(b));
}
__device__ __forceinline__ float2 up2(ull v) {
    float2 f;
    asm("mov.b64 {%0, %1}, %2;" : "=f"(f.x), "=f"(f.y) : "l"(v));
    return f;
}

// ---------------- 8x8 core on PLAIN-float A smem (crossbar-light) ----------------
__device__ __forceinline__ void core16p(const float (*As)[132], const float (*Bs)[68],
                                        int ty8, int tx8, ull acc[8][4]) {
    #pragma unroll
    for (int k = 0; k < 16; k++) {
        float4 a0 = *(const float4*)&As[k][ty8];
        float4 a1 = *(const float4*)&As[k][ty8 + 4];
        ulonglong2 b0 = *(const ulonglong2*)&Bs[k][tx8];
        ulonglong2 b1 = *(const ulonglong2*)&Bs[k][tx8 + 4];
        ull pa;
        pa = pk2(a0.x);
        fma2(acc[0][0], pa, b0.x); fma2(acc[0][1], pa, b0.y);
        fma2(acc[0][2], pa, b1.x); fma2(acc[0][3], pa, b1.y);
        pa = pk2(a0.y);
        fma2(acc[1][0], pa, b0.x); fma2(acc[1][1], pa, b0.y);
        fma2(acc[1][2], pa, b1.x); fma2(acc[1][3], pa, b1.y);
        pa = pk2(a0.z);
        fma2(acc[2][0], pa, b0.x); fma2(acc[2][1], pa, b0.y);
        fma2(acc[2][2], pa, b1.x); fma2(acc[2][3], pa, b1.y);
        pa = pk2(a0.w);
        fma2(acc[3][0], pa, b0.x); fma2(acc[3][1], pa, b0.y);
        fma2(acc[3][2], pa, b1.x); fma2(acc[3][3], pa, b1.y);
        pa = pk2(a1.x);
        fma2(acc[4][0], pa, b0.x); fma2(acc[4][1], pa, b0.y);
        fma2(acc[4][2], pa, b1.x); fma2(acc[4][3], pa, b1.y);
        pa = pk2(a1.y);
        fma2(acc[5][0], pa, b0.x); fma2(acc[5][1], pa, b0.y);
        fma2(acc[5][2], pa, b1.x); fma2(acc[5][3], pa, b1.y);
        pa = pk2(a1.z);
        fma2(acc[6][0], pa, b0.x); fma2(acc[6][1], pa, b0.y);
        fma2(acc[6][2], pa, b1.x); fma2(acc[6][3], pa, b1.y);
        pa = pk2(a1.w);
        fma2(acc[7][0], pa, b0.x); fma2(acc[7][1], pa, b0.y);
        fma2(acc[7][2], pa, b1.x); fma2(acc[7][3], pa, b1.y);
    }
}

__device__ __forceinline__ void stsAp(float (*As)[132], int t, const float4* ra) {
    #pragma unroll
    for (int h = 0; h < 4; h++) {
        As[h * 4 + 0][t] = ra[h].x;
        As[h * 4 + 1][t] = ra[h].y;
        As[h * 4 + 2][t] = ra[h].z;
        As[h * 4 + 3][t] = ra[h].w;
    }
}

// ---------------- generic 128x64 tile GEMM (ldcg loads; Add with own stride) ----------------
__device__ void gtile(float (*As)[132], float (*Bs)[68],
                      const float* __restrict__ A, int lda,
                      const float* __restrict__ B, int ldb,
                      float* __restrict__ C, int ldc,
                      const float* __restrict__ Add, int ldAdd, int K) {
    int t = threadIdx.x;
    int tx8 = (t & 7) * 8, ty8 = (t >> 3) * 8;
    const float* Arow = A + (long)t * lda;
    int kbB = t >> 3, c8B = (t & 7) * 8;
    const float* Bb = B + (long)kbB * ldb + c8B;

    ull acc[8][4];
    #pragma unroll
    for (int i = 0; i < 8; i++)
        #pragma unroll
        for (int jj = 0; jj < 4; jj++) acc[i][jj] = 0ull;

    float4 ra[4], rb0, rb1;
    #pragma unroll
    for (int h = 0; h < 4; h++) ra[h] = __ldcg((const float4*)(Arow + h * 4));
    rb0 = __ldcg((const float4*)Bb);
    rb1 = __ldcg((const float4*)(Bb + 4));
    stsAp(As, t, ra);
    *(float4*)&Bs[kbB][c8B] = rb0;
    *(float4*)&Bs[kbB][c8B + 4] = rb1;
    __syncthreads();

    int KT = K >> 4;
    for (int kt = 0; kt < KT; kt++) {
        int cur = kt & 1;
        bool more = (kt + 1 < KT);
        if (more) {
            int k0 = (kt + 1) * 16;
            #pragma unroll
            for (int h = 0; h < 4; h++) ra[h] = __ldcg((const float4*)(Arow + k0 + h * 4));
            rb0 = __ldcg((const float4*)(Bb + (long)k0 * ldb));
            rb1 = __ldcg((const float4*)(Bb + (long)k0 * ldb + 4));
        }
        core16p(As + cur * 16, Bs + cur * 16, ty8, tx8, acc);
        if (more) {
            stsAp(As + (cur ^ 1) * 16, t, ra);
            *(float4*)&Bs[(cur ^ 1) * 16 + kbB][c8B] = rb0;
            *(float4*)&Bs[(cur ^ 1) * 16 + kbB][c8B + 4] = rb1;
        }
        __syncthreads();
    }

    #pragma unroll
    for (int e = 0; e < 8; e++) {
        float2 x0 = up2(acc[e][0]), x1 = up2(acc[e][1]);
        float2 x2 = up2(acc[e][2]), x3 = up2(acc[e][3]);
        float4 v0 = make_float4(x0.x, x0.y, x1.x, x1.y);
        float4 v1 = make_float4(x2.x, x2.y, x3.x, x3.y);
        long off = (long)(ty8 + e) * ldc + tx8;
        if (Add != nullptr) {
            const float* ap = Add + (long)(ty8 + e) * ldAdd + tx8;
            float4 a0 = __ldcg((const float4*)ap);
            float4 a1 = __ldcg((const float4*)(ap + 4));
            v0.x += a0.x; v0.y += a0.y; v0.z += a0.z; v0.w += a0.w;
            v1.x += a1.x; v1.y += a1.y; v1.z += a1.z; v1.w += a1.w;
        }
        float* cp = C + off;
        *(float4*)cp = v0;
        *(float4*)(cp + 4) = v1;
    }
}

// ---------------- s32 tile: S32[q][:, col0..] = Uchunk_q @ Grev + bL ----------------
__device__ void s32_tile(const float* __restrict__ U, int q, int col0,
                         float (*As)[132], float (*Bs)[68]) {
    int t = threadIdx.x;
    int tx8 = (t & 7) * 8, ty8 = (t >> 3) * 8;
    long uBase = (long)q * (LCH * BB * NU) + (long)t * NU;
    int kbB = t >> 3, c8B = (t & 7) * 8;

    ull acc[8][4];
    #pragma unroll
    for (int i = 0; i < 8; i++)
        #pragma unroll
        for (int jj = 0; jj < 4; jj++) acc[i][jj] = 0ull;

    float4 ra[4], rb0, rb1;
    #pragma unroll
    for (int h = 0; h < 4; h++) {
        int k = h * 4;
        ra[h] = *(const float4*)(U + uBase + (long)(k >> 5) * (BB * NU) + (k & 31));
    }
    {
        const float* brow = d_Gp + (long)((31 - (kbB >> 5)) * NU + (kbB & 31)) * NH + col0 + c8B;
        rb0 = __ldcg((const float4*)brow);
        rb1 = __ldcg((const float4*)(brow + 4));
    }
    stsAp(As, t, ra);
    *(float4*)&Bs[kbB][c8B] = rb0;
    *(float4*)&Bs[kbB][c8B + 4] = rb1;
    __syncthreads();

    const int KT = (LCH * NU) >> 4;  // 64
    for (int kt = 0; kt < KT; kt++) {
        int cur = kt & 1;
        bool more = (kt + 1 < KT);
        if (more) {
            int k0 = (kt + 1) * 16;
            #pragma unroll
            for (int h = 0; h < 4; h++) {
                int k = k0 + h * 4;
                ra[h] = *(const float4*)(U + uBase + (long)(k >> 5) * (BB * NU) + (k & 31));
            }
            int kb = k0 + kbB;
            const float* brow = d_Gp + (long)((31 - (kb >> 5)) * NU + (kb & 31)) * NH + col0 + c8B;
            rb0 = __ldcg((const float4*)brow);
            rb1 = __ldcg((const float4*)(brow + 4));
        }
        core16p(As + cur * 16, Bs + cur * 16, ty8, tx8, acc);
        if (more) {
            stsAp(As + (cur ^ 1) * 16, t, ra);
            *(float4*)&Bs[(cur ^ 1) * 16 + kbB][c8B] = rb0;
            *(float4*)&Bs[(cur ^ 1) * 16 + kbB][c8B + 4] = rb1;
        }
        __syncthreads();
    }

    float4 bl0 = __ldcg((const float4*)&d_Sv[32 * NH + col0 + tx8]);
    float4 bl1 = __ldcg((const float4*)&d_Sv[32 * NH + col0 + tx8 + 4]);
    #pragma unroll
    for (int e = 0; e < 8; e++) {
        int r = ty8 + e;
        float2 x0 = up2(acc[e][0]), x1 = up2(acc[e][1]);
        float2 x2 = up2(acc[e][2]), x3 = up2(acc[e][3]);
        float4 v0 = make_float4(x0.x + bl0.x, x0.y + bl0.y, x1.x + bl0.z, x1.y + bl0.w);
        float4 v1 = make_float4(x2.x + bl1.x, x2.y + bl1.y, x3.x + bl1.z, x3.y + bl1.w);
        float* cp = d_S32 + (long)q * CH + (long)r * NH + col0 + tx8;
        *(float4*)cp = v0;
        *(float4*)(cp + 4) = v1;
    }
}

// ---------------- seq tile: D[32x64 tile] = X @ W + Sp ----------------
__device__ void seq_tile(const float* __restrict__ X, const float* __restrict__ W,
                         const float* __restrict__ Sp, float* __restrict__ D,
                         int row0, int col0, void* sraw) {
    float (*Asq)[36] = (float(*)[36])sraw;
    float (*Bsq)[68] = (float(*)[68])((char*)sraw + 32 * 36 * sizeof(float));
    int t = threadIdx.x;
    int tx8 = (t & 7) * 8;
    int ty2 = (t >> 3) * 2;
    int rA = t >> 2, kqA = (t & 3) * 4;
    int kbB = t >> 3, c8B = (t & 7) * 8;
    const float* Bbase = W + (long)kbB * NH + col0 + c8B;
    const float* Axrow = X + (long)(row0 + rA) * NH;

    ull acc[2][4];
    #pragma unroll
    for (int i = 0; i < 2; i++)
        #pragma unroll
        for (int jj = 0; jj < 4; jj++) acc[i][jj] = 0ull;

    float4 ra, rb0, rb1;
    ra = __ldcg((const float4*)(Axrow + kqA));
    rb0 = __ldcg((const float4*)Bbase);
    rb1 = __ldcg((const float4*)(Bbase + 4));
    Asq[kqA + 0][rA] = ra.x; Asq[kqA + 1][rA] = ra.y;
    Asq[kqA + 2][rA] = ra.z; Asq[kqA + 3][rA] = ra.w;
    *(float4*)&Bsq[kbB][c8B] = rb0;
    *(float4*)&Bsq[kbB][c8B + 4] = rb1;
    __syncthreads();

    const int KT = NH >> 4;  // 32
    for (int kt = 0; kt < KT; kt++) {
        int cur = kt & 1;
        bool more = (kt + 1 < KT);
        if (more) {
            int k0 = (kt + 1) * 16;
            ra = __ldcg((const float4*)(Axrow + k0 + kqA));
            rb0 = __ldcg((const float4*)(Bbase + (long)k0 * NH));
            rb1 = __ldcg((const float4*)(Bbase + (long)k0 * NH + 4));
        }
        #pragma unroll
        for (int k = 0; k < 16; k++) {
            float2 a = *(const float2*)&Asq[cur * 16 + k][ty2];
            ulonglong2 b0 = *(const ulonglong2*)&Bsq[cur * 16 + k][tx8];
            ulonglong2 b1 = *(const ulonglong2*)&Bsq[cur * 16 + k][tx8 + 4];
            ull p0 = pk2(a.x), p1 = pk2(a.y);
            fma2(acc[0][0], p0, b0.x); fma2(acc[0][1], p0, b0.y);
            fma2(acc[0][2], p0, b1.x); fma2(acc[0][3], p0, b1.y);
            fma2(acc[1][0], p1, b0.x); fma2(acc[1][1], p1, b0.y);
            fma2(acc[1][2], p1, b1.x); fma2(acc[1][3], p1, b1.y);
        }
        if (more) {
            int nb = (cur ^ 1) * 16;
            Asq[nb + kqA + 0][rA] = ra.x; Asq[nb + kqA + 1][rA] = ra.y;
            Asq[nb + kqA + 2][rA] = ra.z; Asq[nb + kqA + 3][rA] = ra.w;
            *(float4*)&Bsq[nb + kbB][c8B] = rb0;
            *(float4*)&Bsq[nb + kbB][c8B + 4] = rb1;
        }
        __syncthreads();
    }

    #pragma unroll
    for (int e = 0; e < 2; e++) {
        int r = row0 + ty2 + e;
        float2 x0 = up2(acc[e][0]), x1 = up2(acc[e][1]);
        float2 x2 = up2(acc[e][2]), x3 = up2(acc[e][3]);
        const float* ap = Sp + (long)r * NH + col0 + tx8;
        float4 a0 = __ldcg((const float4*)ap);
        float4 a1 = __ldcg((const float4*)(ap + 4));
        float4 v0 = make_float4(x0.x + a0.x, x0.y + a0.y, x1.x + a0.z, x1.y + a0.w);
        float4 v1 = make_float4(x2.x + a1.x, x2.y + a1.y, x3.x + a1.z, x3.y + a1.w);
        float* dp = D + (long)r * NH + col0 + tx8;
        *(float4*)dp = v0;
        *(float4*)(dp + 4) = v1;
    }
}

// ---------------- grid barrier ----------------
__device__ __forceinline__ void gbar(unsigned& target) {
    __syncthreads();
    __threadfence();
    target += NB;
    if (threadIdx.x == 0) {
        atomicAdd(&d_bar, 1u);
        while (atomicAdd(&d_bar, 0u) < target) {}
    }
    __syncthreads();
}

// ---------------- MEGA kernel (R11 phase structure, 3 blocks/SM) ----------------
__global__ void __launch_bounds__(128, 3) mega_kernel(const float* __restrict__ U,
                                                      const float* __restrict__ x2y_b) {
    __shared__ float As[32][132];
    __shared__ float Bs[32][68];
    int bid = blockIdx.x;
    unsigned target = 0;

    // phases 0-4: powers A^2..A^32, Cbuf/Gp doubling, bias-row doubling
    for (int lvl = 1; lvl <= 5; lvl++) {
        const float* Mp = (lvl == 1) ? d_A : d_Pow[lvl - 2];
        int colTiles = 1 << (lvl - 1);
        int cb = 4 * colTiles;
        int gpRT = (32 << (lvl - 1)) / 128; if (gpRT < 1) gpRT = 1;
        int gp = 8 * gpRT;
        int total = 32 + cb + gp + 8;
        for (int tl = bid; tl < total; tl += NB) {
            if (tl < 32) {
                int row0 = (tl >> 3) * 128, col0 = (tl & 7) * 64;
                gtile(As, Bs, Mp + (long)row0 * NH, NH, Mp + col0, NH,
                      d_Pow[lvl - 1] + (long)row0 * NH + col0, NH, nullptr, 0, NH);
            } else if (tl < 32 + cb) {
                int b = tl - 32;
                int rowTile = b / colTiles, colTile = b % colTiles;
                int row0 = rowTile * 128;
                gtile(As, Bs, Mp + (long)row0 * NH, NH,
                      d_Cbuf + colTile * 64, LDCB,
                      d_Cbuf + (long)row0 * LDCB + (64 << (lvl - 1)) + colTile * 64, LDCB,
                      nullptr, 0, NH);
            } else if (tl < 32 + cb + gp) {
                int b = tl - 32 - cb;
                int rowTile = b >> 3, colTile = b & 7;
                int row0in = rowTile * 128;
                int shift = 32 << (lvl - 1);
                gtile(As, Bs, d_Gp + (long)row0in * NH, NH, Mp + colTile * 64, NH,
                      d_Gp + (long)(row0in + shift) * NH + colTile * 64, NH, nullptr, 0, NH);
            } else {
                int col = tl - 32 - cb - gp;
                int m = 1 << (lvl - 1);
                gtile(As, Bs, d_Sv + NH, NH, Mp + col * 64, NH,
                      d_Sv + (long)(m + 1) * NH + col * 64, NH,
                      d_Sv + (long)m * NH + col * 64, 0, NH);
            }
        }
        gbar(target);
    }

    // phase 5: A^64 squaring (32) + Hd (8) + yb (1) + s32 (512)
    {
        const float* Mp = d_Pow[4];
        for (int tl = bid; tl < 553; tl += NB) {
            if (tl < 32) {
                int row0 = (tl >> 3) * 128, col0 = (tl & 7) * 64;
                gtile(As, Bs, Mp + (long)row0 * NH, NH, Mp + col0, NH,
                      d_Pow[5] + (long)row0 * NH + col0, NH, nullptr, 0, NH);
            } else if (tl < 40) {
                int rowTile = tl - 32;
                gtile(As, Bs, d_Gp + (long)rowTile * 128 * NH, NH, d_Cbuf, LDCB,
                      d_Hd + (long)rowTile * 128 * NY, NY, nullptr, 0, NH);
            } else if (tl < 41) {
                gtile(As, Bs, d_Sv, NH, d_Cbuf, LDCB, d_yb, NY, x2y_b, 0, NH);
            } else {
                int b = tl - 41;
                s32_tile(U, b >> 3, (b & 7) * 64, As, Bs);
            }
        }
        gbar(target);
    }

    // phase 6: A^128 squaring + combine1 (S64)
    {
        const float* Mp = d_Pow[5];
        for (int tl = bid; tl < 32 + 256; tl += NB) {
            if (tl < 32) {
                int row0 = (tl >> 3) * 128, col0 = (tl & 7) * 64;
                gtile(As, Bs, Mp + (long)row0 * NH, NH, Mp + col0, NH,
                      d_Pow[6] + (long)row0 * NH + col0, NH, nullptr, 0, NH);
            } else {
                int b = tl - 32;
                int q = b >> 3, col0 = (b & 7) * 64;
                gtile(As, Bs, d_S32 + 2L * q * CH, NH, d_Pow[4] + col0, NH,
                      d_S64 + (long)q * CH + col0, NH,
                      d_S32 + (2L * q + 1) * CH + col0, NH, NH);
            }
        }
        gbar(target);
    }
    // phase 7: A^256 squaring + combine2 (S128)
    {
        const float* Mp = d_Pow[6];
        for (int tl = bid; tl < 32 + 128; tl += NB) {
            if (tl < 32) {
                int row0 = (tl >> 3) * 128, col0 = (tl & 7) * 64;
                gtile(As, Bs, Mp + (long)row0 * NH, NH, Mp + col0, NH,
                      d_Pow[7] + (long)row0 * NH + col0, NH, nullptr, 0, NH);
            } else {
                int b = tl - 32;
                int q = b >> 3, col0 = (b & 7) * 64;
                gtile(As, Bs, d_S64 + 2L * q * CH, NH, d_Pow[5] + col0, NH,
                      d_S128 + (long)q * CH + col0, NH,
                      d_S64 + (2L * q + 1) * CH + col0, NH, NH);
            }
        }
        gbar(target);
    }
    // phase 8: combine3 (S256)
    {
        for (int tl = bid; tl < 64; tl += NB) {
            int q = tl >> 3, col0 = (tl & 7) * 64;
            gtile(As, Bs, d_S128 + 2L * q * CH, NH, d_Pow[6] + col0, NH,
                  d_S256 + (long)q * CH + col0, NH,
                  d_S128 + (2L * q + 1) * CH + col0, NH, NH);
        }
        gbar(target);
    }
    // phases 9-16: sequential chain, 8 steps of A^256 (32 tiles of 32x64 each)
    for (int s = 0; s < 8; s++) {
        for (int tl = bid; tl < 32; tl += NB) {
            int row0 = (tl >> 3) * 32, col0 = (tl & 7) * 64;
            seq_tile(d_Xc + 8L * s * CH, d_Pow[7], d_S256 + (long)s * CH,
                     d_Xc + 8L * (s + 1) * CH, row0, col0, (void*)As);
        }
        gbar(target);
    }
    // phase 17: fill Xc[8r+4]
    {
        for (int tl = bid; tl < 64; tl += NB) {
            int r = tl >> 3, col0 = (tl & 7) * 64;
            gtile(As, Bs, d_Xc + 8L * r * CH, NH, d_Pow[6] + col0, NH,
                  d_Xc + (8L * r + 4) * CH + col0, NH,
                  d_S128 + 2L * r * CH + col0, NH, NH);
        }
        gbar(target);
    }
    // phase 18: fill Xc[4m+2]
    {
        for (int tl = bid; tl < 128; tl += NB) {
            int m = tl >> 3, col0 = (tl & 7) * 64;
            gtile(As, Bs, d_Xc + 4L * m * CH, NH, d_Pow[5] + col0, NH,
                  d_Xc + (4L * m + 2) * CH + col0, NH,
                  d_S64 + 2L * m * CH + col0, NH, NH);
        }
        gbar(target);
    }
    // phase 19: fill Xc[2n+1]
    {
        for (int tl = bid; tl < 256; tl += NB) {
            int n = tl >> 3, col0 = (tl & 7) * 64;
            gtile(As, Bs, d_Xc + 2L * n * CH, NH, d_Pow[4] + col0, NH,
                  d_Xc + (2L * n + 1) * CH + col0, NH,
                  d_S32 + 2L * n * CH + col0, NH, NH);
        }
    }
}

// ---------------- transpose A ----------------
__global__ void transA_kernel(const float* __restrict__ xu2x_w) {
    __shared__ float tile[32][33];
    int bx = blockIdx.x * 32, by = blockIdx.y * 32;
    int tx = threadIdx.x, ty = threadIdx.y;  // 32 x 8
    #pragma unroll
    for (int r = 0; r < 4; r++)
        tile[ty + r * 8][tx] = xu2x_w[(by + ty + r * 8) * KIN + bx + tx];
    __syncthreads();
    #pragma unroll
    for (int r = 0; r < 4; r++)
        d_A[(bx + ty + r * 8) * NH + by + tx] = tile[tx][ty + r * 8];
}

// ---------------- prep2: Gp0, C0, x0, Sv init, barrier reset ----------------
__global__ void prep2_kernel(const float* __restrict__ y0,
                             const float* __restrict__ y2x_w,
                             const float* __restrict__ y2x_b,
                             const float* __restrict__ xu2x_w,
                             const float* __restrict__ xu2x_b,
                             const float* __restrict__ x2y_w) {
    int idx = blockIdx.x * blockDim.x + threadIdx.x;
    int stride = gridDim.x * blockDim.x;
    if (idx == 0) d_bar = 0u;
    for (int t = idx; t < NU * NH; t += stride) {
        int u = t / NH, h = t % NH;
        d_Gp[u * NH + h] = xu2x_w[h * KIN + NH + u];
    }
    for (int t = idx; t < NH * NY; t += stride) {
        int h = t / NY, n = t % NY;
        d_Cbuf[h * LDCB + n] = x2y_w[n * NH + h];
    }
    for (int t = idx; t < 192 * NH; t += stride) {
        float v = 0.0f;
        if (t >= NH && t < 2 * NH) v = xu2x_b[t - NH];
        d_Sv[t] = v;
    }
    for (int t = idx; t < BB * NH; t += stride) {
        int b = t / NH, h = t % NH;
        float acc = y2x_b[h];
        #pragma unroll 8
        for (int n = 0; n < NY; n++) acc += y0[b * NY + n] * y2x_w[h * NY + n];
        d_Xc[b * NH + h] = acc;
    }
}

// ---------------- output pass (plain-A core, 3 blocks/SM, longest-K-first) ----------------
__global__ void __launch_bounds__(128, 3) out_kernel(const float* __restrict__ U,
                                                     float* __restrict__ out) {
    __shared__ float As[32][132];
    __shared__ float Bs[32][68];
    int bx = blockIdx.x;
    int p, j;
    if (bx == PCH * LCH) { p = PCH; j = 0; }
    else { j = 31 - (bx >> 6); p = bx & 63; }
    int pjOut = p * LCH + j;
    int t = threadIdx.x;
    int KT = 32 + 2 * j;
    int tx8 = (t & 7) * 8, ty8 = (t >> 3) * 8;

    const float* xcRow = d_Xc + (long)p * CH + (long)t * NH;
    long uBase = (long)p * (LCH * BB * NU) + (long)t * NU;
    int kbB = t >> 3, c8B = (t & 7) * 8;

    ull acc[8][4];
    #pragma unroll
    for (int i = 0; i < 8; i++)
        #pragma unroll
        for (int jj = 0; jj < 4; jj++) acc[i][jj] = 0ull;

    float4 ra[4], rb0, rb1;
    #pragma unroll
    for (int h = 0; h < 4; h++) ra[h] = *(const float4*)(xcRow + h * 4);
    {
        const float* brow = d_Cbuf + (long)kbB * LDCB + j * NY + c8B;
        rb0 = *(const float4*)brow;
        rb1 = *(const float4*)(brow + 4);
    }
    stsAp(As, t, ra);
    *(float4*)&Bs[kbB][c8B] = rb0;
    *(float4*)&Bs[kbB][c8B + 4] = rb1;
    __syncthreads();

    for (int kt = 0; kt < KT; kt++) {
        int cur = kt & 1;
        bool more = (kt + 1 < KT);
        if (more) {
            int k0 = (kt + 1) * 16;
            if (k0 < NH) {
                #pragma unroll
                for (int h = 0; h < 4; h++) ra[h] = *(const float4*)(xcRow + k0 + h * 4);
            } else {
                int kc = k0 - NH;
                #pragma unroll
                for (int h = 0; h < 4; h++) {
                    int k = kc + h * 4;
                    ra[h] = *(const float4*)(U + uBase + (long)(k >> 5) * (BB * NU) + (k & 31));
                }
            }
            int kb = k0 + kbB;
            const float* brow;
            if (kb < NH) {
                brow = d_Cbuf + (long)kb * LDCB + j * NY + c8B;
            } else {
                int kc = kb - NH;
                brow = d_Hd + (long)((j - 1 - (kc >> 5)) * NU + (kc & 31)) * NY + c8B;
            }
            rb0 = *(const float4*)brow;
            rb1 = *(const float4*)(brow + 4);
        }
        core16p(As + cur * 16, Bs + cur * 16, ty8, tx8, acc);
        if (more) {
            stsAp(As + (cur ^ 1) * 16, t, ra);
            *(float4*)&Bs[(cur ^ 1) * 16 + kbB][c8B] = rb0;
            *(float4*)&Bs[(cur ^ 1) * 16 + kbB][c8B + 4] = rb1;
        }
        __syncthreads();
    }

    float4 yb0 = *(const float4*)(d_yb + j * NY + tx8);
    float4 yb1 = *(const float4*)(d_yb + j * NY + tx8 + 4);
    float* obase = out + (long)pjOut * (BB * NY);
    #pragma unroll
    for (int e = 0; e < 8; e++) {
        int r = ty8 + e;
        float2 x0 = up2(acc[e][0]), x1 = up2(acc[e][1]);
        float2 x2 = up2(acc[e][2]), x3 = up2(acc[e][3]);
        float4 v0 = make_float4(x0.x + yb0.x, x0.y + yb0.y, x1.x + yb0.z, x1.y + yb0.w);
        float4 v1 = make_float4(x2.x + yb1.x, x2.y + yb1.y, x3.x + yb1.z, x3.y + yb1.w);
        float* op = obase + (long)r * NY + tx8;
        *(float4*)op = v0;
        *(float4*)(op + 4) = v1;
    }
}

// ---------------- host ----------------
extern "C" void kernel_launch(void* const* d_in, const int* in_sizes, int n_in,
                              void* d_out, int out_size) {
    const float* y0     = (const float*)d_in[0];
    const float* U      = (const float*)d_in[1];
    const float* y2x_w  = (const float*)d_in[2];
    const float* y2x_b  = (const float*)d_in[3];
    const float* xu2x_w = (const float*)d_in[4];
    const float* xu2x_b = (const float*)d_in[5];
    const float* x2y_w  = (const float*)d_in[6];
    const float* x2y_b  = (const float*)d_in[7];
    float* out = (float*)d_out;

    // ncu captures overall launch #5 = our 4th (one hidden harness launch ahead).
    transA_kernel<<<dim3(16, 16), dim3(32, 8)>>>(xu2x_w);                  // ours 1
    prep2_kernel<<<128, 256>>>(y0, y2x_w, y2x_b, xu2x_w, xu2x_b, x2y_w);   // ours 2
    mega_kernel<<<NB, 128>>>(U, x2y_b);                                    // ours 3
    out_kernel<<<PCH * LCH + 1, 128>>>(U, out);                            // ours 4 <- profiled
    (void)in_sizes; (void)n_in; (void)out_size;
}

// round 15
// speedup vs baseline: 1.1260x; 1.1260x over previous
#include <cuda_runtime.h>
#include <cstdint>

#define NY 64
#define NU 32
#define NH 512
#define BB 128
#define LCH 32
#define PCH 64
#define KIN 544   // NH + NU
#define CH (BB * NH)
#define LDCB (LCH * NY)   // 2048
#define NB 256            // mega-kernel resident blocks

typedef unsigned long long ull;

// ---------------- device scratch ----------------
__device__ float d_A[NH * NH];
__device__ float d_Pow[8][NH * NH];          // A^2,4,8,16,32,64,128,256
__device__ float d_Cbuf[NH * LCH * NY];      // [512][2048]
__device__ float d_Gp[LCH * NU * NH];        // [1024][512]
__device__ float d_Hd[LCH * NU * NY];        // [1024][64]
__device__ float d_Sv[192 * NH];             // row j = s_j (bias chain)
__device__ float d_yb[128 * NY];             // rows 0..31 valid
__device__ float d_Xc[(PCH + 1) * CH];
__device__ float d_XcT[(PCH + 1) * CH];      // [p][k][m] transposed states
__device__ float d_UT[PCH * LCH * NU * BB];  // [p][kc=i*32+u][b]
__device__ float d_S32[PCH * CH];
__device__ float d_S64[(PCH / 2) * CH];
__device__ float d_S128[(PCH / 4) * CH];
__device__ float d_S256[(PCH / 8) * CH];
__device__ unsigned d_bar;

// ---------------- f32x2 helpers ----------------
__device__ __forceinline__ ull pk2(float x) {
    ull r;
    asm("mov.b64 %0, {%1, %1};" : "=l"(r) : "f"(x));
    return r;
}
__device__ __forceinline__ void fma2(ull& d, ull a, ull b) {
    asm("fma.rn.f32x2 %0, %1, %2, %0;" : "+l"(d) : "l"(a), "l"(b));
}
__device__ __forceinline__ float2 up2(ull v) {
    float2 f;
    asm("mov.b64 {%0, %1}, %2;" : "=f"(f.x), "=f"(f.y) : "l"(v));
    return f;
}

// ---------------- 8x8 core on PLAIN-float A smem ----------------
__device__ __forceinline__ void core16p(const float (*As)[132], const float (*Bs)[68],
                                        int ty8, int tx8, ull acc[8][4]) {
    #pragma unroll
    for (int k = 0; k < 16; k++) {
        float4 a0 = *(const float4*)&As[k][ty8];
        float4 a1 = *(const float4*)&As[k][ty8 + 4];
        ulonglong2 b0 = *(const ulonglong2*)&Bs[k][tx8];
        ulonglong2 b1 = *(const ulonglong2*)&Bs[k][tx8 + 4];
        ull pa;
        pa = pk2(a0.x);
        fma2(acc[0][0], pa, b0.x); fma2(acc[0][1], pa, b0.y);
        fma2(acc[0][2], pa, b1.x); fma2(acc[0][3], pa, b1.y);
        pa = pk2(a0.y);
        fma2(acc[1][0], pa, b0.x); fma2(acc[1][1], pa, b0.y);
        fma2(acc[1][2], pa, b1.x); fma2(acc[1][3], pa, b1.y);
        pa = pk2(a0.z);
        fma2(acc[2][0], pa, b0.x); fma2(acc[2][1], pa, b0.y);
        fma2(acc[2][2], pa, b1.x); fma2(acc[2][3], pa, b1.y);
        pa = pk2(a0.w);
        fma2(acc[3][0], pa, b0.x); fma2(acc[3][1], pa, b0.y);
        fma2(acc[3][2], pa, b1.x); fma2(acc[3][3], pa, b1.y);
        pa = pk2(a1.x);
        fma2(acc[4][0], pa, b0.x); fma2(acc[4][1], pa, b0.y);
        fma2(acc[4][2], pa, b1.x); fma2(acc[4][3], pa, b1.y);
        pa = pk2(a1.y);
        fma2(acc[5][0], pa, b0.x); fma2(acc[5][1], pa, b0.y);
        fma2(acc[5][2], pa, b1.x); fma2(acc[5][3], pa, b1.y);
        pa = pk2(a1.z);
        fma2(acc[6][0], pa, b0.x); fma2(acc[6][1], pa, b0.y);
        fma2(acc[6][2], pa, b1.x); fma2(acc[6][3], pa, b1.y);
        pa = pk2(a1.w);
        fma2(acc[7][0], pa, b0.x); fma2(acc[7][1], pa, b0.y);
        fma2(acc[7][2], pa, b1.x); fma2(acc[7][3], pa, b1.y);
    }
}

__device__ __forceinline__ void stsAp(float (*As)[132], int t, const float4* ra) {
    #pragma unroll
    for (int h = 0; h < 4; h++) {
        As[h * 4 + 0][t] = ra[h].x;
        As[h * 4 + 1][t] = ra[h].y;
        As[h * 4 + 2][t] = ra[h].z;
        As[h * 4 + 3][t] = ra[h].w;
    }
}

// k-major vector store: thread covers row kS, cols mq+32i (conflict-free)
__device__ __forceinline__ void stsA4(float (*As)[132], int kS, int mq, const float4* ra) {
    #pragma unroll
    for (int i = 0; i < 4; i++)
        *(float4*)&As[kS][mq + i * 32] = ra[i];
}

// ---------------- generic 128x64 tile GEMM (row-major A; precompute paths) ----------------
__device__ void gtile(float (*As)[132], float (*Bs)[68],
                      const float* __restrict__ A, int lda,
                      const float* __restrict__ B, int ldb,
                      float* __restrict__ C, int ldc,
                      const float* __restrict__ Add, int ldAdd, int K) {
    int t = threadIdx.x;
    int tx8 = (t & 7) * 8, ty8 = (t >> 3) * 8;
    const float* Arow = A + (long)t * lda;
    int kbB = t >> 3, c8B = (t & 7) * 8;
    const float* Bb = B + (long)kbB * ldb + c8B;

    ull acc[8][4];
    #pragma unroll
    for (int i = 0; i < 8; i++)
        #pragma unroll
        for (int jj = 0; jj < 4; jj++) acc[i][jj] = 0ull;

    float4 ra[4], rb0, rb1;
    #pragma unroll
    for (int h = 0; h < 4; h++) ra[h] = __ldcg((const float4*)(Arow + h * 4));
    rb0 = __ldcg((const float4*)Bb);
    rb1 = __ldcg((const float4*)(Bb + 4));
    stsAp(As, t, ra);
    *(float4*)&Bs[kbB][c8B] = rb0;
    *(float4*)&Bs[kbB][c8B + 4] = rb1;
    __syncthreads();

    int KT = K >> 4;
    for (int kt = 0; kt < KT; kt++) {
        int cur = kt & 1;
        bool more = (kt + 1 < KT);
        if (more) {
            int k0 = (kt + 1) * 16;
            #pragma unroll
            for (int h = 0; h < 4; h++) ra[h] = __ldcg((const float4*)(Arow + k0 + h * 4));
            rb0 = __ldcg((const float4*)(Bb + (long)k0 * ldb));
            rb1 = __ldcg((const float4*)(Bb + (long)k0 * ldb + 4));
        }
        core16p(As + cur * 16, Bs + cur * 16, ty8, tx8, acc);
        if (more) {
            stsAp(As + (cur ^ 1) * 16, t, ra);
            *(float4*)&Bs[(cur ^ 1) * 16 + kbB][c8B] = rb0;
            *(float4*)&Bs[(cur ^ 1) * 16 + kbB][c8B + 4] = rb1;
        }
        __syncthreads();
    }

    #pragma unroll
    for (int e = 0; e < 8; e++) {
        float2 x0 = up2(acc[e][0]), x1 = up2(acc[e][1]);
        float2 x2 = up2(acc[e][2]), x3 = up2(acc[e][3]);
        float4 v0 = make_float4(x0.x, x0.y, x1.x, x1.y);
        float4 v1 = make_float4(x2.x, x2.y, x3.x, x3.y);
        long off = (long)(ty8 + e) * ldc + tx8;
        if (Add != nullptr) {
            const float* ap = Add + (long)(ty8 + e) * ldAdd + tx8;
            float4 a0 = __ldcg((const float4*)ap);
            float4 a1 = __ldcg((const float4*)(ap + 4));
            v0.x += a0.x; v0.y += a0.y; v0.z += a0.z; v0.w += a0.w;
            v1.x += a1.x; v1.y += a1.y; v1.z += a1.z; v1.w += a1.w;
        }
        float* cp = C + off;
        *(float4*)cp = v0;
        *(float4*)(cp + 4) = v1;
    }
}

// ---------------- s32 tile (A from UT, k-major coalesced) ----------------
__device__ void s32_tile(int q, int col0, float (*As)[132], float (*Bs)[68]) {
    int t = threadIdx.x;
    int tx8 = (t & 7) * 8, ty8 = (t >> 3) * 8;
    int kS = t >> 3, mq = (t & 7) * 4;
    const float* uBase = d_UT + (long)q * (LCH * NU * BB);
    int kbB = t >> 3, c8B = (t & 7) * 8;

    ull acc[8][4];
    #pragma unroll
    for (int i = 0; i < 8; i++)
        #pragma unroll
        for (int jj = 0; jj < 4; jj++) acc[i][jj] = 0ull;

    float4 ra[4], rb0, rb1;
    {
        const float* src = uBase + (long)kS * BB + mq;
        #pragma unroll
        for (int i = 0; i < 4; i++) ra[i] = __ldcg((const float4*)(src + i * 32));
        const float* brow = d_Gp + (long)((31 - (kbB >> 5)) * NU + (kbB & 31)) * NH + col0 + c8B;
        rb0 = __ldcg((const float4*)brow);
        rb1 = __ldcg((const float4*)(brow + 4));
    }
    stsA4(As, kS, mq, ra);
    *(float4*)&Bs[kbB][c8B] = rb0;
    *(float4*)&Bs[kbB][c8B + 4] = rb1;
    __syncthreads();

    const int KT = (LCH * NU) >> 4;  // 64
    for (int kt = 0; kt < KT; kt++) {
        int cur = kt & 1;
        bool more = (kt + 1 < KT);
        if (more) {
            int k0 = (kt + 1) * 16;
            const float* src = uBase + (long)(k0 + kS) * BB + mq;
            #pragma unroll
            for (int i = 0; i < 4; i++) ra[i] = __ldcg((const float4*)(src + i * 32));
            int kb = k0 + kbB;
            const float* brow = d_Gp + (long)((31 - (kb >> 5)) * NU + (kb & 31)) * NH + col0 + c8B;
            rb0 = __ldcg((const float4*)brow);
            rb1 = __ldcg((const float4*)(brow + 4));
        }
        core16p(As + cur * 16, Bs + cur * 16, ty8, tx8, acc);
        if (more) {
            stsA4(As + (cur ^ 1) * 16, kS, mq, ra);
            *(float4*)&Bs[(cur ^ 1) * 16 + kbB][c8B] = rb0;
            *(float4*)&Bs[(cur ^ 1) * 16 + kbB][c8B + 4] = rb1;
        }
        __syncthreads();
    }

    float4 bl0 = __ldcg((const float4*)&d_Sv[32 * NH + col0 + tx8]);
    float4 bl1 = __ldcg((const float4*)&d_Sv[32 * NH + col0 + tx8 + 4]);
    #pragma unroll
    for (int e = 0; e < 8; e++) {
        int r = ty8 + e;
        float2 x0 = up2(acc[e][0]), x1 = up2(acc[e][1]);
        float2 x2 = up2(acc[e][2]), x3 = up2(acc[e][3]);
        float4 v0 = make_float4(x0.x + bl0.x, x0.y + bl0.y, x1.x + bl0.z, x1.y + bl0.w);
        float4 v1 = make_float4(x2.x + bl1.x, x2.y + bl1.y, x3.x + bl1.z, x3.y + bl1.w);
        float* cp = d_S32 + (long)q * CH + (long)r * NH + col0 + tx8;
        *(float4*)cp = v0;
        *(float4*)(cp + 4) = v1;
    }
}

// ---------------- seq tile: D[32x64 tile] = X @ W + Sp ----------------
__device__ void seq_tile(const float* __restrict__ X, const float* __restrict__ W,
                         const float* __restrict__ Sp, float* __restrict__ D,
                         int row0, int col0, void* sraw) {
    float (*Asq)[36] = (float(*)[36])sraw;
    float (*Bsq)[68] = (float(*)[68])((char*)sraw + 32 * 36 * sizeof(float));
    int t = threadIdx.x;
    int tx8 = (t & 7) * 8;
    int ty2 = (t >> 3) * 2;
    int rA = t >> 2, kqA = (t & 3) * 4;
    int kbB = t >> 3, c8B = (t & 7) * 8;
    const float* Bbase = W + (long)kbB * NH + col0 + c8B;
    const float* Axrow = X + (long)(row0 + rA) * NH;

    ull acc[2][4];
    #pragma unroll
    for (int i = 0; i < 2; i++)
        #pragma unroll
        for (int jj = 0; jj < 4; jj++) acc[i][jj] = 0ull;

    float4 ra, rb0, rb1;
    ra = __ldcg((const float4*)(Axrow + kqA));
    rb0 = __ldcg((const float4*)Bbase);
    rb1 = __ldcg((const float4*)(Bbase + 4));
    Asq[kqA + 0][rA] = ra.x; Asq[kqA + 1][rA] = ra.y;
    Asq[kqA + 2][rA] = ra.z; Asq[kqA + 3][rA] = ra.w;
    *(float4*)&Bsq[kbB][c8B] = rb0;
    *(float4*)&Bsq[kbB][c8B + 4] = rb1;
    __syncthreads();

    const int KT = NH >> 4;  // 32
    for (int kt = 0; kt < KT; kt++) {
        int cur = kt & 1;
        bool more = (kt + 1 < KT);
        if (more) {
            int k0 = (kt + 1) * 16;
            ra = __ldcg((const float4*)(Axrow + k0 + kqA));
            rb0 = __ldcg((const float4*)(Bbase + (long)k0 * NH));
            rb1 = __ldcg((const float4*)(Bbase + (long)k0 * NH + 4));
        }
        #pragma unroll
        for (int k = 0; k < 16; k++) {
            float2 a = *(const float2*)&Asq[cur * 16 + k][ty2];
            ulonglong2 b0 = *(const ulonglong2*)&Bsq[cur * 16 + k][tx8];
            ulonglong2 b1 = *(const ulonglong2*)&Bsq[cur * 16 + k][tx8 + 4];
            ull p0 = pk2(a.x), p1 = pk2(a.y);
            fma2(acc[0][0], p0, b0.x); fma2(acc[0][1], p0, b0.y);
            fma2(acc[0][2], p0, b1.x); fma2(acc[0][3], p0, b1.y);
            fma2(acc[1][0], p1, b0.x); fma2(acc[1][1], p1, b0.y);
            fma2(acc[1][2], p1, b1.x); fma2(acc[1][3], p1, b1.y);
        }
        if (more) {
            int nb = (cur ^ 1) * 16;
            Asq[nb + kqA + 0][rA] = ra.x; Asq[nb + kqA + 1][rA] = ra.y;
            Asq[nb + kqA + 2][rA] = ra.z; Asq[nb + kqA + 3][rA] = ra.w;
            *(float4*)&Bsq[nb + kbB][c8B] = rb0;
            *(float4*)&Bsq[nb + kbB][c8B + 4] = rb1;
        }
        __syncthreads();
    }

    #pragma unroll
    for (int e = 0; e < 2; e++) {
        int r = row0 + ty2 + e;
        float2 x0 = up2(acc[e][0]), x1 = up2(acc[e][1]);
        float2 x2 = up2(acc[e][2]), x3 = up2(acc[e][3]);
        const float* ap = Sp + (long)r * NH + col0 + tx8;
        float4 a0 = __ldcg((const float4*)ap);
        float4 a1 = __ldcg((const float4*)(ap + 4));
        float4 v0 = make_float4(x0.x + a0.x, x0.y + a0.y, x1.x + a0.z, x1.y + a0.w);
        float4 v1 = make_float4(x2.x + a1.x, x2.y + a1.y, x3.x + a1.z, x3.y + a1.w);
        float* dp = D + (long)r * NH + col0 + tx8;
        *(float4*)dp = v0;
        *(float4*)(dp + 4) = v1;
    }
}

// ---------------- grid barrier ----------------
__device__ __forceinline__ void gbar(unsigned& target) {
    __syncthreads();
    __threadfence();
    target += NB;
    if (threadIdx.x == 0) {
        atomicAdd(&d_bar, 1u);
        while (atomicAdd(&d_bar, 0u) < target) {}
    }
    __syncthreads();
}

// ---------------- MEGA kernel ----------------
__global__ void __launch_bounds__(128, 2) mega_kernel(const float* __restrict__ x2y_b) {
    __shared__ float As[32][132];
    __shared__ float Bs[32][68];
    int bid = blockIdx.x;
    unsigned target = 0;

    // phases 0-4: powers A^2..A^32, Cbuf/Gp doubling, bias-row doubling
    for (int lvl = 1; lvl <= 5; lvl++) {
        const float* Mp = (lvl == 1) ? d_A : d_Pow[lvl - 2];
        int colTiles = 1 << (lvl - 1);
        int cb = 4 * colTiles;
        int gpRT = (32 << (lvl - 1)) / 128; if (gpRT < 1) gpRT = 1;
        int gp = 8 * gpRT;
        int total = 32 + cb + gp + 8;
        for (int tl = bid; tl < total; tl += NB) {
            if (tl < 32) {
                int row0 = (tl >> 3) * 128, col0 = (tl & 7) * 64;
                gtile(As, Bs, Mp + (long)row0 * NH, NH, Mp + col0, NH,
                      d_Pow[lvl - 1] + (long)row0 * NH + col0, NH, nullptr, 0, NH);
            } else if (tl < 32 + cb) {
                int b = tl - 32;
                int rowTile = b / colTiles, colTile = b % colTiles;
                int row0 = rowTile * 128;
                gtile(As, Bs, Mp + (long)row0 * NH, NH,
                      d_Cbuf + colTile * 64, LDCB,
                      d_Cbuf + (long)row0 * LDCB + (64 << (lvl - 1)) + colTile * 64, LDCB,
                      nullptr, 0, NH);
            } else if (tl < 32 + cb + gp) {
                int b = tl - 32 - cb;
                int rowTile = b >> 3, colTile = b & 7;
                int row0in = rowTile * 128;
                int shift = 32 << (lvl - 1);
                gtile(As, Bs, d_Gp + (long)row0in * NH, NH, Mp + colTile * 64, NH,
                      d_Gp + (long)(row0in + shift) * NH + colTile * 64, NH, nullptr, 0, NH);
            } else {
                int col = tl - 32 - cb - gp;
                int m = 1 << (lvl - 1);
                gtile(As, Bs, d_Sv + NH, NH, Mp + col * 64, NH,
                      d_Sv + (long)(m + 1) * NH + col * 64, NH,
                      d_Sv + (long)m * NH + col * 64, 0, NH);
            }
        }
        gbar(target);
    }

    // phase 5: A^64 squaring (32) + Hd (8) + yb (1) + s32 (512)
    {
        const float* Mp = d_Pow[4];
        for (int tl = bid; tl < 553; tl += NB) {
            if (tl < 32) {
                int row0 = (tl >> 3) * 128, col0 = (tl & 7) * 64;
                gtile(As, Bs, Mp + (long)row0 * NH, NH, Mp + col0, NH,
                      d_Pow[5] + (long)row0 * NH + col0, NH, nullptr, 0, NH);
            } else if (tl < 40) {
                int rowTile = tl - 32;
                gtile(As, Bs, d_Gp + (long)rowTile * 128 * NH, NH, d_Cbuf, LDCB,
                      d_Hd + (long)rowTile * 128 * NY, NY, nullptr, 0, NH);
            } else if (tl < 41) {
                gtile(As, Bs, d_Sv, NH, d_Cbuf, LDCB, d_yb, NY, x2y_b, 0, NH);
            } else {
                int b = tl - 41;
                s32_tile(b >> 3, (b & 7) * 64, As, Bs);
            }
        }
        gbar(target);
    }

    // phase 6: A^128 squaring + combine1 (S64)
    {
        const float* Mp = d_Pow[5];
        for (int tl = bid; tl < 32 + 256; tl += NB) {
            if (tl < 32) {
                int row0 = (tl >> 3) * 128, col0 = (tl & 7) * 64;
                gtile(As, Bs, Mp + (long)row0 * NH, NH, Mp + col0, NH,
                      d_Pow[6] + (long)row0 * NH + col0, NH, nullptr, 0, NH);
            } else {
                int b = tl - 32;
                int q = b >> 3, col0 = (b & 7) * 64;
                gtile(As, Bs, d_S32 + 2L * q * CH, NH, d_Pow[4] + col0, NH,
                      d_S64 + (long)q * CH + col0, NH,
                      d_S32 + (2L * q + 1) * CH + col0, NH, NH);
            }
        }
        gbar(target);
    }
    // phase 7: A^256 squaring + combine2 (S128)
    {
        const float* Mp = d_Pow[6];
        for (int tl = bid; tl < 32 + 128; tl += NB) {
            if (tl < 32) {
                int row0 = (tl >> 3) * 128, col0 = (tl & 7) * 64;
                gtile(As, Bs, Mp + (long)row0 * NH, NH, Mp + col0, NH,
                      d_Pow[7] + (long)row0 * NH + col0, NH, nullptr, 0, NH);
            } else {
                int b = tl - 32;
                int q = b >> 3, col0 = (b & 7) * 64;
                gtile(As, Bs, d_S64 + 2L * q * CH, NH, d_Pow[5] + col0, NH,
                      d_S128 + (long)q * CH + col0, NH,
                      d_S64 + (2L * q + 1) * CH + col0, NH, NH);
            }
        }
        gbar(target);
    }
    // phase 8: combine3 (S256)
    {
        for (int tl = bid; tl < 64; tl += NB) {
            int q = tl >> 3, col0 = (tl & 7) * 64;
            gtile(As, Bs, d_S128 + 2L * q * CH, NH, d_Pow[6] + col0, NH,
                  d_S256 + (long)q * CH + col0, NH,
                  d_S128 + (2L * q + 1) * CH + col0, NH, NH);
        }
        gbar(target);
    }
    // phases 9-16: sequential chain, 8 steps of A^256
    for (int s = 0; s < 8; s++) {
        for (int tl = bid; tl < 32; tl += NB) {
            int row0 = (tl >> 3) * 32, col0 = (tl & 7) * 64;
            seq_tile(d_Xc + 8L * s * CH, d_Pow[7], d_S256 + (long)s * CH,
                     d_Xc + 8L * (s + 1) * CH, row0, col0, (void*)As);
        }
        gbar(target);
    }
    // phase 17: fill Xc[8r+4]
    {
        for (int tl = bid; tl < 64; tl += NB) {
            int r = tl >> 3, col0 = (tl & 7) * 64;
            gtile(As, Bs, d_Xc + 8L * r * CH, NH, d_Pow[6] + col0, NH,
                  d_Xc + (8L * r + 4) * CH + col0, NH,
                  d_S128 + 2L * r * CH + col0, NH, NH);
        }
        gbar(target);
    }
    // phase 18: fill Xc[4m+2]
    {
        for (int tl = bid; tl < 128; tl += NB) {
            int m = tl >> 3, col0 = (tl & 7) * 64;
            gtile(As, Bs, d_Xc + 4L * m * CH, NH, d_Pow[5] + col0, NH,
                  d_Xc + (4L * m + 2) * CH + col0, NH,
                  d_S64 + 2L * m * CH + col0, NH, NH);
        }
        gbar(target);
    }
    // phase 19: fill Xc[2n+1]
    {
        for (int tl = bid; tl < 256; tl += NB) {
            int n = tl >> 3, col0 = (tl & 7) * 64;
            gtile(As, Bs, d_Xc + 2L * n * CH, NH, d_Pow[4] + col0, NH,
                  d_Xc + (2L * n + 1) * CH + col0, NH,
                  d_S32 + 2L * n * CH + col0, NH, NH);
        }
        gbar(target);
    }
    // phase 20: transpose all 65 states Xc -> XcT ([m][k] -> [k][m])
    {
        float (*tt)[33] = (float(*)[33])((void*)As);
        int t = threadIdx.x;
        int tx = t & 31, tyy = t >> 5;  // 32 x 4
        for (int tl = bid; tl < 65 * 64; tl += NB) {
            int s = tl >> 6;
            int rem = tl & 63;
            int kt0 = (rem >> 2) * 32, mt0 = (rem & 3) * 32;
            const float* src = d_Xc + (long)s * CH;
            float* dst = d_XcT + (long)s * CH;
            __syncthreads();
            #pragma unroll
            for (int r = 0; r < 8; r++) {
                int m = mt0 + tyy * 8 + r;
                tt[tyy * 8 + r][tx] = __ldcg(src + (long)m * NH + kt0 + tx);
            }
            __syncthreads();
            #pragma unroll
            for (int r = 0; r < 8; r++) {
                int k = kt0 + tyy * 8 + r;
                dst[(long)k * BB + mt0 + tx] = tt[tx][tyy * 8 + r];
            }
        }
    }
}

// ---------------- transpose A + transpose U ----------------
__global__ void transAU_kernel(const float* __restrict__ xu2x_w,
                               const float* __restrict__ U) {
    int b = blockIdx.x;
    int t = threadIdx.x;
    if (b < 256) {
        __shared__ float tile[32][33];
        int bx = (b & 15) * 32, by = (b >> 4) * 32;
        int tx = t & 31, ty = t >> 5;  // 32 x 8
        #pragma unroll
        for (int r = 0; r < 4; r++)
            tile[ty + r * 8][tx] = xu2x_w[(long)(by + ty + r * 8) * KIN + bx + tx];
        __syncthreads();
        #pragma unroll
        for (int r = 0; r < 4; r++)
            d_A[(long)(bx + ty + r * 8) * NH + by + tx] = tile[tx][ty + r * 8];
    } else {
        // U slice transpose: slice = (p, i) in [0, 2048): [128 b][32 u] -> UT[p][i*32+u][b]
        __shared__ float tile[128][33];
        int slice = b - 256;  // 0..2047
        const float* src = U + (long)slice * (BB * NU);
        float* dst = d_UT + (long)slice * (NU * BB);
        int u = t & 31, brow = t >> 5;  // 32 x 8
        #pragma unroll
        for (int r = 0; r < 16; r++)
            tile[brow + r * 8][u] = src[(long)(brow + r * 8) * NU + u];
        __syncthreads();
        int uo = t >> 3, mb = (t & 7) * 16;
        #pragma unroll
        for (int c = 0; c < 16; c++)
            dst[(long)uo * BB + mb + c] = tile[mb + c][uo];
    }
}

// ---------------- prep2: Gp0, C0, x0, Sv init, barrier reset ----------------
__global__ void prep2_kernel(const float* __restrict__ y0,
                             const float* __restrict__ y2x_w,
                             const float* __restrict__ y2x_b,
                             const float* __restrict__ xu2x_w,
                             const float* __restrict__ xu2x_b,
                             const float* __restrict__ x2y_w) {
    int idx = blockIdx.x * blockDim.x + threadIdx.x;
    int stride = gridDim.x * blockDim.x;
    if (idx == 0) d_bar = 0u;
    for (int t = idx; t < NU * NH; t += stride) {
        int u = t / NH, h = t % NH;
        d_Gp[u * NH + h] = xu2x_w[h * KIN + NH + u];
    }
    for (int t = idx; t < NH * NY; t += stride) {
        int h = t / NY, n = t % NY;
        d_Cbuf[h * LDCB + n] = x2y_w[n * NH + h];
    }
    for (int t = idx; t < 192 * NH; t += stride) {
        float v = 0.0f;
        if (t >= NH && t < 2 * NH) v = xu2x_b[t - NH];
        d_Sv[t] = v;
    }
    for (int t = idx; t < BB * NH; t += stride) {
        int b = t / NH, h = t % NH;
        float acc = y2x_b[h];
        #pragma unroll 8
        for (int n = 0; n < NY; n++) acc += y0[b * NY + n] * y2x_w[h * NY + n];
        d_Xc[b * NH + h] = acc;
    }
}

// ---------------- output pass (k-major A from XcT/UT) ----------------
__global__ void __launch_bounds__(128, 3) out_kernel(float* __restrict__ out) {
    __shared__ float As[32][132];
    __shared__ float Bs[32][68];
    int bx = blockIdx.x;
    int p, j;
    if (bx == PCH * LCH) { p = PCH; j = 0; }
    else { j = 31 - (bx >> 6); p = bx & 63; }
    int pjOut = p * LCH + j;
    int t = threadIdx.x;
    int KT = 32 + 2 * j;
    int tx8 = (t & 7) * 8, ty8 = (t >> 3) * 8;

    int kS = t >> 3, mq = (t & 7) * 4;
    const float* xT = d_XcT + (long)p * CH;
    const float* uT = d_UT + (long)p * (LCH * NU * BB);
    int kbB = t >> 3, c8B = (t & 7) * 8;

    ull acc[8][4];
    #pragma unroll
    for (int i = 0; i < 8; i++)
        #pragma unroll
        for (int jj = 0; jj < 4; jj++) acc[i][jj] = 0ull;

    float4 ra[4], rb0, rb1;
    {
        const float* src = xT + (long)kS * BB + mq;
        #pragma unroll
        for (int i = 0; i < 4; i++) ra[i] = __ldcg((const float4*)(src + i * 32));
        const float* brow = d_Cbuf + (long)kbB * LDCB + j * NY + c8B;
        rb0 = *(const float4*)brow;
        rb1 = *(const float4*)(brow + 4);
    }
    stsA4(As, kS, mq, ra);
    *(float4*)&Bs[kbB][c8B] = rb0;
    *(float4*)&Bs[kbB][c8B + 4] = rb1;
    __syncthreads();

    for (int kt = 0; kt < KT; kt++) {
        int cur = kt & 1;
        bool more = (kt + 1 < KT);
        if (more) {
            int k0 = (kt + 1) * 16;
            const float* src = (k0 < NH)
                ? xT + (long)(k0 + kS) * BB + mq
                : uT + (long)(k0 - NH + kS) * BB + mq;
            #pragma unroll
            for (int i = 0; i < 4; i++) ra[i] = __ldcg((const float4*)(src + i * 32));
            int kb = k0 + kbB;
            const float* brow;
            if (kb < NH) {
                brow = d_Cbuf + (long)kb * LDCB + j * NY + c8B;
            } else {
                int kc = kb - NH;
                brow = d_Hd + (long)((j - 1 - (kc >> 5)) * NU + (kc & 31)) * NY + c8B;
            }
            rb0 = *(const float4*)brow;
            rb1 = *(const float4*)(brow + 4);
        }
        core16p(As + cur * 16, Bs + cur * 16, ty8, tx8, acc);
        if (more) {
            stsA4(As + (cur ^ 1) * 16, kS, mq, ra);
            *(float4*)&Bs[(cur ^ 1) * 16 + kbB][c8B] = rb0;
            *(float4*)&Bs[(cur ^ 1) * 16 + kbB][c8B + 4] = rb1;
        }
        __syncthreads();
    }

    float4 yb0 = *(const float4*)(d_yb + j * NY + tx8);
    float4 yb1 = *(const float4*)(d_yb + j * NY + tx8 + 4);
    float* obase = out + (long)pjOut * (BB * NY);
    #pragma unroll
    for (int e = 0; e < 8; e++) {
        int r = ty8 + e;
        float2 x0 = up2(acc[e][0]), x1 = up2(acc[e][1]);
        float2 x2 = up2(acc[e][2]), x3 = up2(acc[e][3]);
        float4 v0 = make_float4(x0.x + yb0.x, x0.y + yb0.y, x1.x + yb0.z, x1.y + yb0.w);
        float4 v1 = make_float4(x2.x + yb1.x, x2.y + yb1.y, x3.x + yb1.z, x3.y + yb1.w);
        float* op = obase + (long)r * NY + tx8;
        *(float4*)op = v0;
        *(float4*)(op + 4) = v1;
    }
}

// ---------------- host ----------------
extern "C" void kernel_launch(void* const* d_in, const int* in_sizes, int n_in,
                              void* d_out, int out_size) {
    const float* y0     = (const float*)d_in[0];
    const float* U      = (const float*)d_in[1];
    const float* y2x_w  = (const float*)d_in[2];
    const float* y2x_b  = (const float*)d_in[3];
    const float* xu2x_w = (const float*)d_in[4];
    const float* xu2x_b = (const float*)d_in[5];
    const float* x2y_w  = (const float*)d_in[6];
    const float* x2y_b  = (const float*)d_in[7];
    float* out = (float*)d_out;

    // ncu captures overall launch #5 = our 4th.
    transAU_kernel<<<256 + 2048, 256>>>(xu2x_w, U);                        // ours 1 (2048 U slices!)
    prep2_kernel<<<128, 256>>>(y0, y2x_w, y2x_b, xu2x_w, xu2x_b, x2y_w);   // ours 2
    mega_kernel<<<NB, 128>>>(x2y_b);                                       // ours 3
    out_kernel<<<PCH * LCH + 1, 128>>>(out);                               // ours 4 <- profiled
    (void)in_sizes; (void)n_in; (void)out_size;
}

// round 16
// speedup vs baseline: 1.1963x; 1.0625x over previous
#include <cuda_runtime.h>
#include <cstdint>

#define NY 64
#define NU 32
#define NH 512
#define BB 128
#define LCH 32
#define PCH 64
#define KIN 544   // NH + NU
#define CH (BB * NH)
#define LDCB (LCH * NY)   // 2048
#define NB 256            // mega-kernel resident blocks

typedef unsigned long long ull;

// ---------------- device scratch ----------------
__device__ float d_A[NH * NH];
__device__ float d_Pow[8][NH * NH];          // A^2,4,8,16,32,64,128,256
__device__ float d_Cbuf[NH * LCH * NY];      // [512][2048]
__device__ float d_Gp[LCH * NU * NH];        // [1024][512]
__device__ float d_Hd[LCH * NU * NY];        // [1024][64]
__device__ float d_Sv[192 * NH];             // row j = s_j (bias chain)
__device__ float d_yb[128 * NY];             // rows 0..31 valid
__device__ float d_Xc[(PCH + 1) * CH];
__device__ float d_XcT[(PCH + 1) * CH];      // [p][k][m] transposed states
__device__ float d_UT[PCH * LCH * NU * BB];  // [p][kc=i*32+u][b]
__device__ float d_S32[PCH * CH];
__device__ float d_S64[(PCH / 2) * CH];
__device__ float d_S128[(PCH / 4) * CH];
__device__ float d_S256[(PCH / 8) * CH];
__device__ unsigned d_bar;

// ---------------- f32x2 helpers ----------------
__device__ __forceinline__ ull pk2(float x) {
    ull r;
    asm("mov.b64 %0, {%1, %1};" : "=l"(r) : "f"(x));
    return r;
}
__device__ __forceinline__ void fma2(ull& d, ull a, ull b) {
    asm("fma.rn.f32x2 %0, %1, %2, %0;" : "+l"(d) : "l"(a), "l"(b));
}
__device__ __forceinline__ float2 up2(ull v) {
    float2 f;
    asm("mov.b64 {%0, %1}, %2;" : "=f"(f.x), "=f"(f.y) : "l"(v));
    return f;
}

// ---------------- 8x8 core on PLAIN-float A smem ----------------
__device__ __forceinline__ void core16p(const float (*As)[132], const float (*Bs)[68],
                                        int ty8, int tx8, ull acc[8][4]) {
    #pragma unroll
    for (int k = 0; k < 16; k++) {
        float4 a0 = *(const float4*)&As[k][ty8];
        float4 a1 = *(const float4*)&As[k][ty8 + 4];
        ulonglong2 b0 = *(const ulonglong2*)&Bs[k][tx8];
        ulonglong2 b1 = *(const ulonglong2*)&Bs[k][tx8 + 4];
        ull pa;
        pa = pk2(a0.x);
        fma2(acc[0][0], pa, b0.x); fma2(acc[0][1], pa, b0.y);
        fma2(acc[0][2], pa, b1.x); fma2(acc[0][3], pa, b1.y);
        pa = pk2(a0.y);
        fma2(acc[1][0], pa, b0.x); fma2(acc[1][1], pa, b0.y);
        fma2(acc[1][2], pa, b1.x); fma2(acc[1][3], pa, b1.y);
        pa = pk2(a0.z);
        fma2(acc[2][0], pa, b0.x); fma2(acc[2][1], pa, b0.y);
        fma2(acc[2][2], pa, b1.x); fma2(acc[2][3], pa, b1.y);
        pa = pk2(a0.w);
        fma2(acc[3][0], pa, b0.x); fma2(acc[3][1], pa, b0.y);
        fma2(acc[3][2], pa, b1.x); fma2(acc[3][3], pa, b1.y);
        pa = pk2(a1.x);
        fma2(acc[4][0], pa, b0.x); fma2(acc[4][1], pa, b0.y);
        fma2(acc[4][2], pa, b1.x); fma2(acc[4][3], pa, b1.y);
        pa = pk2(a1.y);
        fma2(acc[5][0], pa, b0.x); fma2(acc[5][1], pa, b0.y);
        fma2(acc[5][2], pa, b1.x); fma2(acc[5][3], pa, b1.y);
        pa = pk2(a1.z);
        fma2(acc[6][0], pa, b0.x); fma2(acc[6][1], pa, b0.y);
        fma2(acc[6][2], pa, b1.x); fma2(acc[6][3], pa, b1.y);
        pa = pk2(a1.w);
        fma2(acc[7][0], pa, b0.x); fma2(acc[7][1], pa, b0.y);
        fma2(acc[7][2], pa, b1.x); fma2(acc[7][3], pa, b1.y);
    }
}

// k-major vector store for out/s32 (thread covers row kS, cols mq+32i)
__device__ __forceinline__ void stsA4(float (*As)[132], int kS, int mq, const float4* ra) {
    #pragma unroll
    for (int i = 0; i < 4; i++)
        *(float4*)&As[kS][mq + i * 32] = ra[i];
}

// coalesced-gtile store: thread holds (m = mA + h*32, k = kqA..kqA+3)
__device__ __forceinline__ void stsAg(float (*As)[132], int kqA, int mA, const float4* ra) {
    #pragma unroll
    for (int h = 0; h < 4; h++) {
        int m = mA + h * 32;
        As[kqA + 0][m] = ra[h].x;
        As[kqA + 1][m] = ra[h].y;
        As[kqA + 2][m] = ra[h].z;
        As[kqA + 3][m] = ra[h].w;
    }
}

// ---------------- generic 128x64 tile GEMM (row-major A, coalesced loads) ----------------
__device__ void gtile(float (*As)[132], float (*Bs)[68],
                      const float* __restrict__ A, int lda,
                      const float* __restrict__ B, int ldb,
                      float* __restrict__ C, int ldc,
                      const float* __restrict__ Add, int ldAdd, int K) {
    int t = threadIdx.x;
    int tx8 = (t & 7) * 8, ty8 = (t >> 3) * 8;
    int mA = t >> 2, kqA = (t & 3) * 4;      // warp covers 8 rows x 16 k -> 8 lines/LDG
    const float* Abase = A + (long)mA * lda + kqA;
    int kbB = t >> 3, c8B = (t & 7) * 8;
    const float* Bb = B + (long)kbB * ldb + c8B;

    ull acc[8][4];
    #pragma unroll
    for (int i = 0; i < 8; i++)
        #pragma unroll
        for (int jj = 0; jj < 4; jj++) acc[i][jj] = 0ull;

    float4 ra[4], rb0, rb1;
    #pragma unroll
    for (int h = 0; h < 4; h++) ra[h] = __ldcg((const float4*)(Abase + (long)h * 32 * lda));
    rb0 = __ldcg((const float4*)Bb);
    rb1 = __ldcg((const float4*)(Bb + 4));
    stsAg(As, kqA, mA, ra);
    *(float4*)&Bs[kbB][c8B] = rb0;
    *(float4*)&Bs[kbB][c8B + 4] = rb1;
    __syncthreads();

    int KT = K >> 4;
    for (int kt = 0; kt < KT; kt++) {
        int cur = kt & 1;
        bool more = (kt + 1 < KT);
        if (more) {
            int k0 = (kt + 1) * 16;
            #pragma unroll
            for (int h = 0; h < 4; h++)
                ra[h] = __ldcg((const float4*)(Abase + k0 + (long)h * 32 * lda));
            rb0 = __ldcg((const float4*)(Bb + (long)k0 * ldb));
            rb1 = __ldcg((const float4*)(Bb + (long)k0 * ldb + 4));
        }
        core16p(As + cur * 16, Bs + cur * 16, ty8, tx8, acc);
        if (more) {
            stsAg(As + (cur ^ 1) * 16, kqA, mA, ra);
            *(float4*)&Bs[(cur ^ 1) * 16 + kbB][c8B] = rb0;
            *(float4*)&Bs[(cur ^ 1) * 16 + kbB][c8B + 4] = rb1;
        }
        __syncthreads();
    }

    #pragma unroll
    for (int e = 0; e < 8; e++) {
        float2 x0 = up2(acc[e][0]), x1 = up2(acc[e][1]);
        float2 x2 = up2(acc[e][2]), x3 = up2(acc[e][3]);
        float4 v0 = make_float4(x0.x, x0.y, x1.x, x1.y);
        float4 v1 = make_float4(x2.x, x2.y, x3.x, x3.y);
        long off = (long)(ty8 + e) * ldc + tx8;
        if (Add != nullptr) {
            const float* ap = Add + (long)(ty8 + e) * ldAdd + tx8;
            float4 a0 = __ldcg((const float4*)ap);
            float4 a1 = __ldcg((const float4*)(ap + 4));
            v0.x += a0.x; v0.y += a0.y; v0.z += a0.z; v0.w += a0.w;
            v1.x += a1.x; v1.y += a1.y; v1.z += a1.z; v1.w += a1.w;
        }
        float* cp = C + off;
        *(float4*)cp = v0;
        *(float4*)(cp + 4) = v1;
    }
}

// ---------------- s32 tile (A from UT, k-major coalesced) ----------------
__device__ void s32_tile(int q, int col0, float (*As)[132], float (*Bs)[68]) {
    int t = threadIdx.x;
    int tx8 = (t & 7) * 8, ty8 = (t >> 3) * 8;
    int kS = t >> 3, mq = (t & 7) * 4;
    const float* uBase = d_UT + (long)q * (LCH * NU * BB);
    int kbB = t >> 3, c8B = (t & 7) * 8;

    ull acc[8][4];
    #pragma unroll
    for (int i = 0; i < 8; i++)
        #pragma unroll
        for (int jj = 0; jj < 4; jj++) acc[i][jj] = 0ull;

    float4 ra[4], rb0, rb1;
    {
        const float* src = uBase + (long)kS * BB + mq;
        #pragma unroll
        for (int i = 0; i < 4; i++) ra[i] = __ldcg((const float4*)(src + i * 32));
        const float* brow = d_Gp + (long)((31 - (kbB >> 5)) * NU + (kbB & 31)) * NH + col0 + c8B;
        rb0 = __ldcg((const float4*)brow);
        rb1 = __ldcg((const float4*)(brow + 4));
    }
    stsA4(As, kS, mq, ra);
    *(float4*)&Bs[kbB][c8B] = rb0;
    *(float4*)&Bs[kbB][c8B + 4] = rb1;
    __syncthreads();

    const int KT = (LCH * NU) >> 4;  // 64
    for (int kt = 0; kt < KT; kt++) {
        int cur = kt & 1;
        bool more = (kt + 1 < KT);
        if (more) {
            int k0 = (kt + 1) * 16;
            const float* src = uBase + (long)(k0 + kS) * BB + mq;
            #pragma unroll
            for (int i = 0; i < 4; i++) ra[i] = __ldcg((const float4*)(src + i * 32));
            int kb = k0 + kbB;
            const float* brow = d_Gp + (long)((31 - (kb >> 5)) * NU + (kb & 31)) * NH + col0 + c8B;
            rb0 = __ldcg((const float4*)brow);
            rb1 = __ldcg((const float4*)(brow + 4));
        }
        core16p(As + cur * 16, Bs + cur * 16, ty8, tx8, acc);
        if (more) {
            stsA4(As + (cur ^ 1) * 16, kS, mq, ra);
            *(float4*)&Bs[(cur ^ 1) * 16 + kbB][c8B] = rb0;
            *(float4*)&Bs[(cur ^ 1) * 16 + kbB][c8B + 4] = rb1;
        }
        __syncthreads();
    }

    float4 bl0 = __ldcg((const float4*)&d_Sv[32 * NH + col0 + tx8]);
    float4 bl1 = __ldcg((const float4*)&d_Sv[32 * NH + col0 + tx8 + 4]);
    #pragma unroll
    for (int e = 0; e < 8; e++) {
        int r = ty8 + e;
        float2 x0 = up2(acc[e][0]), x1 = up2(acc[e][1]);
        float2 x2 = up2(acc[e][2]), x3 = up2(acc[e][3]);
        float4 v0 = make_float4(x0.x + bl0.x, x0.y + bl0.y, x1.x + bl0.z, x1.y + bl0.w);
        float4 v1 = make_float4(x2.x + bl1.x, x2.y + bl1.y, x3.x + bl1.z, x3.y + bl1.w);
        float* cp = d_S32 + (long)q * CH + (long)r * NH + col0 + tx8;
        *(float4*)cp = v0;
        *(float4*)(cp + 4) = v1;
    }
}

// ---------------- seq tile: D[32x64 tile] = X @ W + Sp ----------------
__device__ void seq_tile(const float* __restrict__ X, const float* __restrict__ W,
                         const float* __restrict__ Sp, float* __restrict__ D,
                         int row0, int col0, void* sraw) {
    float (*Asq)[36] = (float(*)[36])sraw;
    float (*Bsq)[68] = (float(*)[68])((char*)sraw + 32 * 36 * sizeof(float));
    int t = threadIdx.x;
    int tx8 = (t & 7) * 8;
    int ty2 = (t >> 3) * 2;
    int rA = t >> 2, kqA = (t & 3) * 4;
    int kbB = t >> 3, c8B = (t & 7) * 8;
    const float* Bbase = W + (long)kbB * NH + col0 + c8B;
    const float* Axrow = X + (long)(row0 + rA) * NH;

    ull acc[2][4];
    #pragma unroll
    for (int i = 0; i < 2; i++)
        #pragma unroll
        for (int jj = 0; jj < 4; jj++) acc[i][jj] = 0ull;

    float4 ra, rb0, rb1;
    ra = __ldcg((const float4*)(Axrow + kqA));
    rb0 = __ldcg((const float4*)Bbase);
    rb1 = __ldcg((const float4*)(Bbase + 4));
    Asq[kqA + 0][rA] = ra.x; Asq[kqA + 1][rA] = ra.y;
    Asq[kqA + 2][rA] = ra.z; Asq[kqA + 3][rA] = ra.w;
    *(float4*)&Bsq[kbB][c8B] = rb0;
    *(float4*)&Bsq[kbB][c8B + 4] = rb1;
    __syncthreads();

    const int KT = NH >> 4;  // 32
    for (int kt = 0; kt < KT; kt++) {
        int cur = kt & 1;
        bool more = (kt + 1 < KT);
        if (more) {
            int k0 = (kt + 1) * 16;
            ra = __ldcg((const float4*)(Axrow + k0 + kqA));
            rb0 = __ldcg((const float4*)(Bbase + (long)k0 * NH));
            rb1 = __ldcg((const float4*)(Bbase + (long)k0 * NH + 4));
        }
        #pragma unroll
        for (int k = 0; k < 16; k++) {
            float2 a = *(const float2*)&Asq[cur * 16 + k][ty2];
            ulonglong2 b0 = *(const ulonglong2*)&Bsq[cur * 16 + k][tx8];
            ulonglong2 b1 = *(const ulonglong2*)&Bsq[cur * 16 + k][tx8 + 4];
            ull p0 = pk2(a.x), p1 = pk2(a.y);
            fma2(acc[0][0], p0, b0.x); fma2(acc[0][1], p0, b0.y);
            fma2(acc[0][2], p0, b1.x); fma2(acc[0][3], p0, b1.y);
            fma2(acc[1][0], p1, b0.x); fma2(acc[1][1], p1, b0.y);
            fma2(acc[1][2], p1, b1.x); fma2(acc[1][3], p1, b1.y);
        }
        if (more) {
            int nb = (cur ^ 1) * 16;
            Asq[nb + kqA + 0][rA] = ra.x; Asq[nb + kqA + 1][rA] = ra.y;
            Asq[nb + kqA + 2][rA] = ra.z; Asq[nb + kqA + 3][rA] = ra.w;
            *(float4*)&Bsq[nb + kbB][c8B] = rb0;
            *(float4*)&Bsq[nb + kbB][c8B + 4] = rb1;
        }
        __syncthreads();
    }

    #pragma unroll
    for (int e = 0; e < 2; e++) {
        int r = row0 + ty2 + e;
        float2 x0 = up2(acc[e][0]), x1 = up2(acc[e][1]);
        float2 x2 = up2(acc[e][2]), x3 = up2(acc[e][3]);
        const float* ap = Sp + (long)r * NH + col0 + tx8;
        float4 a0 = __ldcg((const float4*)ap);
        float4 a1 = __ldcg((const float4*)(ap + 4));
        float4 v0 = make_float4(x0.x + a0.x, x0.y + a0.y, x1.x + a0.z, x1.y + a0.w);
        float4 v1 = make_float4(x2.x + a1.x, x2.y + a1.y, x3.x + a1.z, x3.y + a1.w);
        float* dp = D + (long)r * NH + col0 + tx8;
        *(float4*)dp = v0;
        *(float4*)(dp + 4) = v1;
    }
}

// ---------------- grid barrier ----------------
__device__ __forceinline__ void gbar(unsigned& target) {
    __syncthreads();
    __threadfence();
    target += NB;
    if (threadIdx.x == 0) {
        atomicAdd(&d_bar, 1u);
        while (atomicAdd(&d_bar, 0u) < target) {}
    }
    __syncthreads();
}

// ---------------- MEGA kernel ----------------
__global__ void __launch_bounds__(128, 2) mega_kernel(const float* __restrict__ x2y_b) {
    __shared__ float As[32][132];
    __shared__ float Bs[32][68];
    int bid = blockIdx.x;
    unsigned target = 0;

    // phases 0-4: powers A^2..A^32, Cbuf/Gp doubling, bias-row doubling
    for (int lvl = 1; lvl <= 5; lvl++) {
        const float* Mp = (lvl == 1) ? d_A : d_Pow[lvl - 2];
        int colTiles = 1 << (lvl - 1);
        int cb = 4 * colTiles;
        int gpRT = (32 << (lvl - 1)) / 128; if (gpRT < 1) gpRT = 1;
        int gp = 8 * gpRT;
        int total = 32 + cb + gp + 8;
        for (int tl = bid; tl < total; tl += NB) {
            if (tl < 32) {
                int row0 = (tl >> 3) * 128, col0 = (tl & 7) * 64;
                gtile(As, Bs, Mp + (long)row0 * NH, NH, Mp + col0, NH,
                      d_Pow[lvl - 1] + (long)row0 * NH + col0, NH, nullptr, 0, NH);
            } else if (tl < 32 + cb) {
                int b = tl - 32;
                int rowTile = b / colTiles, colTile = b % colTiles;
                int row0 = rowTile * 128;
                gtile(As, Bs, Mp + (long)row0 * NH, NH,
                      d_Cbuf + colTile * 64, LDCB,
                      d_Cbuf + (long)row0 * LDCB + (64 << (lvl - 1)) + colTile * 64, LDCB,
                      nullptr, 0, NH);
            } else if (tl < 32 + cb + gp) {
                int b = tl - 32 - cb;
                int rowTile = b >> 3, colTile = b & 7;
                int row0in = rowTile * 128;
                int shift = 32 << (lvl - 1);
                gtile(As, Bs, d_Gp + (long)row0in * NH, NH, Mp + colTile * 64, NH,
                      d_Gp + (long)(row0in + shift) * NH + colTile * 64, NH, nullptr, 0, NH);
            } else {
                int col = tl - 32 - cb - gp;
                int m = 1 << (lvl - 1);
                gtile(As, Bs, d_Sv + NH, NH, Mp + col * 64, NH,
                      d_Sv + (long)(m + 1) * NH + col * 64, NH,
                      d_Sv + (long)m * NH + col * 64, 0, NH);
            }
        }
        gbar(target);
    }

    // phase 5: A^64 squaring (32) + Hd (8) + yb (1) + s32 (512)
    {
        const float* Mp = d_Pow[4];
        for (int tl = bid; tl < 553; tl += NB) {
            if (tl < 32) {
                int row0 = (tl >> 3) * 128, col0 = (tl & 7) * 64;
                gtile(As, Bs, Mp + (long)row0 * NH, NH, Mp + col0, NH,
                      d_Pow[5] + (long)row0 * NH + col0, NH, nullptr, 0, NH);
            } else if (tl < 40) {
                int rowTile = tl - 32;
                gtile(As, Bs, d_Gp + (long)rowTile * 128 * NH, NH, d_Cbuf, LDCB,
                      d_Hd + (long)rowTile * 128 * NY, NY, nullptr, 0, NH);
            } else if (tl < 41) {
                gtile(As, Bs, d_Sv, NH, d_Cbuf, LDCB, d_yb, NY, x2y_b, 0, NH);
            } else {
                int b = tl - 41;
                s32_tile(b >> 3, (b & 7) * 64, As, Bs);
            }
        }
        gbar(target);
    }

    // phase 6: A^128 squaring + combine1 (S64)
    {
        const float* Mp = d_Pow[5];
        for (int tl = bid; tl < 32 + 256; tl += NB) {
            if (tl < 32) {
                int row0 = (tl >> 3) * 128, col0 = (tl & 7) * 64;
                gtile(As, Bs, Mp + (long)row0 * NH, NH, Mp + col0, NH,
                      d_Pow[6] + (long)row0 * NH + col0, NH, nullptr, 0, NH);
            } else {
                int b = tl - 32;
                int q = b >> 3, col0 = (b & 7) * 64;
                gtile(As, Bs, d_S32 + 2L * q * CH, NH, d_Pow[4] + col0, NH,
                      d_S64 + (long)q * CH + col0, NH,
                      d_S32 + (2L * q + 1) * CH + col0, NH, NH);
            }
        }
        gbar(target);
    }
    // phase 7: A^256 squaring + combine2 (S128)
    {
        const float* Mp = d_Pow[6];
        for (int tl = bid; tl < 32 + 128; tl += NB) {
            if (tl < 32) {
                int row0 = (tl >> 3) * 128, col0 = (tl & 7) * 64;
                gtile(As, Bs, Mp + (long)row0 * NH, NH, Mp + col0, NH,
                      d_Pow[7] + (long)row0 * NH + col0, NH, nullptr, 0, NH);
            } else {
                int b = tl - 32;
                int q = b >> 3, col0 = (b & 7) * 64;
                gtile(As, Bs, d_S64 + 2L * q * CH, NH, d_Pow[5] + col0, NH,
                      d_S128 + (long)q * CH + col0, NH,
                      d_S64 + (2L * q + 1) * CH + col0, NH, NH);
            }
        }
        gbar(target);
    }
    // phase 8: combine3 (S256)
    {
        for (int tl = bid; tl < 64; tl += NB) {
            int q = tl >> 3, col0 = (tl & 7) * 64;
            gtile(As, Bs, d_S128 + 2L * q * CH, NH, d_Pow[6] + col0, NH,
                  d_S256 + (long)q * CH + col0, NH,
                  d_S128 + (2L * q + 1) * CH + col0, NH, NH);
        }
        gbar(target);
    }
    // phases 9-16: sequential chain, 8 steps of A^256
    for (int s = 0; s < 8; s++) {
        for (int tl = bid; tl < 32; tl += NB) {
            int row0 = (tl >> 3) * 32, col0 = (tl & 7) * 64;
            seq_tile(d_Xc + 8L * s * CH, d_Pow[7], d_S256 + (long)s * CH,
                     d_Xc + 8L * (s + 1) * CH, row0, col0, (void*)As);
        }
        gbar(target);
    }
    // phase 17: fill Xc[8r+4]
    {
        for (int tl = bid; tl < 64; tl += NB) {
            int r = tl >> 3, col0 = (tl & 7) * 64;
            gtile(As, Bs, d_Xc + 8L * r * CH, NH, d_Pow[6] + col0, NH,
                  d_Xc + (8L * r + 4) * CH + col0, NH,
                  d_S128 + 2L * r * CH + col0, NH, NH);
        }
        gbar(target);
    }
    // phase 18: fill Xc[4m+2]
    {
        for (int tl = bid; tl < 128; tl += NB) {
            int m = tl >> 3, col0 = (tl & 7) * 64;
            gtile(As, Bs, d_Xc + 4L * m * CH, NH, d_Pow[5] + col0, NH,
                  d_Xc + (4L * m + 2) * CH + col0, NH,
                  d_S64 + 2L * m * CH + col0, NH, NH);
        }
        gbar(target);
    }
    // phase 19: fill Xc[2n+1]
    {
        for (int tl = bid; tl < 256; tl += NB) {
            int n = tl >> 3, col0 = (tl & 7) * 64;
            gtile(As, Bs, d_Xc + 2L * n * CH, NH, d_Pow[4] + col0, NH,
                  d_Xc + (2L * n + 1) * CH + col0, NH,
                  d_S32 + 2L * n * CH + col0, NH, NH);
        }
        gbar(target);
    }
    // phase 20: transpose all 65 states Xc -> XcT ([m][k] -> [k][m])
    {
        float (*tt)[33] = (float(*)[33])((void*)As);
        int t = threadIdx.x;
        int tx = t & 31, tyy = t >> 5;  // 32 x 4
        for (int tl = bid; tl < 65 * 64; tl += NB) {
            int s = tl >> 6;
            int rem = tl & 63;
            int kt0 = (rem >> 2) * 32, mt0 = (rem & 3) * 32;
            const float* src = d_Xc + (long)s * CH;
            float* dst = d_XcT + (long)s * CH;
            __syncthreads();
            #pragma unroll
            for (int r = 0; r < 8; r++) {
                int m = mt0 + tyy * 8 + r;
                tt[tyy * 8 + r][tx] = __ldcg(src + (long)m * NH + kt0 + tx);
            }
            __syncthreads();
            #pragma unroll
            for (int r = 0; r < 8; r++) {
                int k = kt0 + tyy * 8 + r;
                dst[(long)k * BB + mt0 + tx] = tt[tx][tyy * 8 + r];
            }
        }
    }
}

// ---------------- transpose A + transpose U ----------------
__global__ void transAU_kernel(const float* __restrict__ xu2x_w,
                               const float* __restrict__ U) {
    int b = blockIdx.x;
    int t = threadIdx.x;
    if (b < 256) {
        __shared__ float tile[32][33];
        int bx = (b & 15) * 32, by = (b >> 4) * 32;
        int tx = t & 31, ty = t >> 5;  // 32 x 8
        #pragma unroll
        for (int r = 0; r < 4; r++)
            tile[ty + r * 8][tx] = xu2x_w[(long)(by + ty + r * 8) * KIN + bx + tx];
        __syncthreads();
        #pragma unroll
        for (int r = 0; r < 4; r++)
            d_A[(long)(bx + ty + r * 8) * NH + by + tx] = tile[tx][ty + r * 8];
    } else {
        // U slice transpose: slice in [0, 2048): [128 b][32 u] -> UT[p][i*32+u][b]
        __shared__ float tile[128][33];
        int slice = b - 256;
        const float* src = U + (long)slice * (BB * NU);
        float* dst = d_UT + (long)slice * (NU * BB);
        int u = t & 31, brow = t >> 5;  // 32 x 8
        #pragma unroll
        for (int r = 0; r < 16; r++)
            tile[brow + r * 8][u] = src[(long)(brow + r * 8) * NU + u];
        __syncthreads();
        int uo = t >> 3, mb = (t & 7) * 16;
        #pragma unroll
        for (int c = 0; c < 16; c++)
            dst[(long)uo * BB + mb + c] = tile[mb + c][uo];
    }
}

// ---------------- prep2: Gp0, C0, x0, Sv init, barrier reset ----------------
__global__ void prep2_kernel(const float* __restrict__ y0,
                             const float* __restrict__ y2x_w,
                             const float* __restrict__ y2x_b,
                             const float* __restrict__ xu2x_w,
                             const float* __restrict__ xu2x_b,
                             const float* __restrict__ x2y_w) {
    int idx = blockIdx.x * blockDim.x + threadIdx.x;
    int stride = gridDim.x * blockDim.x;
    if (idx == 0) d_bar = 0u;
    for (int t = idx; t < NU * NH; t += stride) {
        int u = t / NH, h = t % NH;
        d_Gp[u * NH + h] = xu2x_w[h * KIN + NH + u];
    }
    for (int t = idx; t < NH * NY; t += stride) {
        int h = t / NY, n = t % NY;
        d_Cbuf[h * LDCB + n] = x2y_w[n * NH + h];
    }
    for (int t = idx; t < 192 * NH; t += stride) {
        float v = 0.0f;
        if (t >= NH && t < 2 * NH) v = xu2x_b[t - NH];
        d_Sv[t] = v;
    }
    for (int t = idx; t < BB * NH; t += stride) {
        int b = t / NH, h = t % NH;
        float acc = y2x_b[h];
        #pragma unroll 8
        for (int n = 0; n < NY; n++) acc += y0[b * NY + n] * y2x_w[h * NY + n];
        d_Xc[b * NH + h] = acc;
    }
}

// ---------------- output pass (k-major A from XcT/UT) ----------------
__global__ void __launch_bounds__(128, 3) out_kernel(float* __restrict__ out) {
    __shared__ float As[32][132];
    __shared__ float Bs[32][68];
    int bx = blockIdx.x;
    int p, j;
    if (bx == PCH * LCH) { p = PCH; j = 0; }
    else { j = 31 - (bx >> 6); p = bx & 63; }
    int pjOut = p * LCH + j;
    int t = threadIdx.x;
    int KT = 32 + 2 * j;
    int tx8 = (t & 7) * 8, ty8 = (t >> 3) * 8;

    int kS = t >> 3, mq = (t & 7) * 4;
    const float* xT = d_XcT + (long)p * CH;
    const float* uT = d_UT + (long)p * (LCH * NU * BB);
    int kbB = t >> 3, c8B = (t & 7) * 8;

    ull acc[8][4];
    #pragma unroll
    for (int i = 0; i < 8; i++)
        #pragma unroll
        for (int jj = 0; jj < 4; jj++) acc[i][jj] = 0ull;

    float4 ra[4], rb0, rb1;
    {
        const float* src = xT + (long)kS * BB + mq;
        #pragma unroll
        for (int i = 0; i < 4; i++) ra[i] = __ldcg((const float4*)(src + i * 32));
        const float* brow = d_Cbuf + (long)kbB * LDCB + j * NY + c8B;
        rb0 = *(const float4*)brow;
        rb1 = *(const float4*)(brow + 4);
    }
    stsA4(As, kS, mq, ra);
    *(float4*)&Bs[kbB][c8B] = rb0;
    *(float4*)&Bs[kbB][c8B + 4] = rb1;
    __syncthreads();

    for (int kt = 0; kt < KT; kt++) {
        int cur = kt & 1;
        bool more = (kt + 1 < KT);
        if (more) {
            int k0 = (kt + 1) * 16;
            const float* src = (k0 < NH)
                ? xT + (long)(k0 + kS) * BB + mq
                : uT + (long)(k0 - NH + kS) * BB + mq;
            #pragma unroll
            for (int i = 0; i < 4; i++) ra[i] = __ldcg((const float4*)(src + i * 32));
            int kb = k0 + kbB;
            const float* brow;
            if (kb < NH) {
                brow = d_Cbuf + (long)kb * LDCB + j * NY + c8B;
            } else {
                int kc = kb - NH;
                brow = d_Hd + (long)((j - 1 - (kc >> 5)) * NU + (kc & 31)) * NY + c8B;
            }
            rb0 = *(const float4*)brow;
            rb1 = *(const float4*)(brow + 4);
        }
        core16p(As + cur * 16, Bs + cur * 16, ty8, tx8, acc);
        if (more) {
            stsA4(As + (cur ^ 1) * 16, kS, mq, ra);
            *(float4*)&Bs[(cur ^ 1) * 16 + kbB][c8B] = rb0;
            *(float4*)&Bs[(cur ^ 1) * 16 + kbB][c8B + 4] = rb1;
        }
        __syncthreads();
    }

    float4 yb0 = *(const float4*)(d_yb + j * NY + tx8);
    float4 yb1 = *(const float4*)(d_yb + j * NY + tx8 + 4);
    float* obase = out + (long)pjOut * (BB * NY);
    #pragma unroll
    for (int e = 0; e < 8; e++) {
        int r = ty8 + e;
        float2 x0 = up2(acc[e][0]), x1 = up2(acc[e][1]);
        float2 x2 = up2(acc[e][2]), x3 = up2(acc[e][3]);
        float4 v0 = make_float4(x0.x + yb0.x, x0.y + yb0.y, x1.x + yb0.z, x1.y + yb0.w);
        float4 v1 = make_float4(x2.x + yb1.x, x2.y + yb1.y, x3.x + yb1.z, x3.y + yb1.w);
        float* op = obase + (long)r * NY + tx8;
        *(float4*)op = v0;
        *(float4*)(op + 4) = v1;
    }
}

// ---------------- host ----------------
extern "C" void kernel_launch(void* const* d_in, const int* in_sizes, int n_in,
                              void* d_out, int out_size) {
    const float* y0     = (const float*)d_in[0];
    const float* U      = (const float*)d_in[1];
    const float* y2x_w  = (const float*)d_in[2];
    const float* y2x_b  = (const float*)d_in[3];
    const float* xu2x_w = (const float*)d_in[4];
    const float* xu2x_b = (const float*)d_in[5];
    const float* x2y_w  = (const float*)d_in[6];
    const float* x2y_b  = (const float*)d_in[7];
    float* out = (float*)d_out;

    // ncu captures overall launch #5 = our 4th.
    transAU_kernel<<<256 + 2048, 256>>>(xu2x_w, U);                        // ours 1
    prep2_kernel<<<128, 256>>>(y0, y2x_w, y2x_b, xu2x_w, xu2x_b, x2y_w);   // ours 2
    mega_kernel<<<NB, 128>>>(x2y_b);                                       // ours 3
    out_kernel<<<PCH * LCH + 1, 128>>>(out);                               // ours 4 <- profiled
    (void)in_sizes; (void)n_in; (void)out_size;
}

// round 17
// speedup vs baseline: 1.2344x; 1.0319x over previous
#include <cuda_runtime.h>
#include <cstdint>

#define NY 64
#define NU 32
#define NH 512
#define BB 128
#define LCH 32
#define PCH 64
#define KIN 544   // NH + NU
#define CH (BB * NH)
#define LDCB (LCH * NY)   // 2048
#define NB 296            // mega-kernel resident blocks (148 SMs x 2)

typedef unsigned long long ull;

// ---------------- device scratch ----------------
__device__ float d_A[NH * NH];
__device__ float d_Pow[8][NH * NH];          // A^2,4,8,16,32,64,128,256
__device__ float d_Cbuf[NH * LCH * NY];      // [512][2048]
__device__ float d_Gp[LCH * NU * NH];        // [1024][512]
__device__ float d_Hd[LCH * NU * NY];        // [1024][64]
__device__ float d_Sv[192 * NH];             // row j = s_j (bias chain)
__device__ float d_yb[128 * NY];             // rows 0..31 valid
__device__ float d_Xc[(PCH + 1) * CH];
__device__ float d_XcT[(PCH + 1) * CH];      // [p][k][m] transposed states
__device__ float d_UT[PCH * LCH * NU * BB];  // [p][kc=i*32+u][b]
__device__ float d_S32[PCH * CH];
__device__ float d_S64[(PCH / 2) * CH];
__device__ float d_S128[(PCH / 4) * CH];
__device__ float d_S256[(PCH / 8) * CH];
__device__ unsigned d_bar;

// ---------------- f32x2 helpers ----------------
__device__ __forceinline__ ull pk2(float x) {
    ull r;
    asm("mov.b64 %0, {%1, %1};" : "=l"(r) : "f"(x));
    return r;
}
__device__ __forceinline__ void fma2(ull& d, ull a, ull b) {
    asm("fma.rn.f32x2 %0, %1, %2, %0;" : "+l"(d) : "l"(a), "l"(b));
}
__device__ __forceinline__ float2 up2(ull v) {
    float2 f;
    asm("mov.b64 {%0, %1}, %2;" : "=f"(f.x), "=f"(f.y) : "l"(v));
    return f;
}

// ---------------- 8x8 core on PLAIN-float A smem ----------------
__device__ __forceinline__ void core16p(const float (*As)[132], const float (*Bs)[68],
                                        int ty8, int tx8, ull acc[8][4]) {
    #pragma unroll
    for (int k = 0; k < 16; k++) {
        float4 a0 = *(const float4*)&As[k][ty8];
        float4 a1 = *(const float4*)&As[k][ty8 + 4];
        ulonglong2 b0 = *(const ulonglong2*)&Bs[k][tx8];
        ulonglong2 b1 = *(const ulonglong2*)&Bs[k][tx8 + 4];
        ull pa;
        pa = pk2(a0.x);
        fma2(acc[0][0], pa, b0.x); fma2(acc[0][1], pa, b0.y);
        fma2(acc[0][2], pa, b1.x); fma2(acc[0][3], pa, b1.y);
        pa = pk2(a0.y);
        fma2(acc[1][0], pa, b0.x); fma2(acc[1][1], pa, b0.y);
        fma2(acc[1][2], pa, b1.x); fma2(acc[1][3], pa, b1.y);
        pa = pk2(a0.z);
        fma2(acc[2][0], pa, b0.x); fma2(acc[2][1], pa, b0.y);
        fma2(acc[2][2], pa, b1.x); fma2(acc[2][3], pa, b1.y);
        pa = pk2(a0.w);
        fma2(acc[3][0], pa, b0.x); fma2(acc[3][1], pa, b0.y);
        fma2(acc[3][2], pa, b1.x); fma2(acc[3][3], pa, b1.y);
        pa = pk2(a1.x);
        fma2(acc[4][0], pa, b0.x); fma2(acc[4][1], pa, b0.y);
        fma2(acc[4][2], pa, b1.x); fma2(acc[4][3], pa, b1.y);
        pa = pk2(a1.y);
        fma2(acc[5][0], pa, b0.x); fma2(acc[5][1], pa, b0.y);
        fma2(acc[5][2], pa, b1.x); fma2(acc[5][3], pa, b1.y);
        pa = pk2(a1.z);
        fma2(acc[6][0], pa, b0.x); fma2(acc[6][1], pa, b0.y);
        fma2(acc[6][2], pa, b1.x); fma2(acc[6][3], pa, b1.y);
        pa = pk2(a1.w);
        fma2(acc[7][0], pa, b0.x); fma2(acc[7][1], pa, b0.y);
        fma2(acc[7][2], pa, b1.x); fma2(acc[7][3], pa, b1.y);
    }
}

// k-major vector store for out/s32 (thread covers row kS, cols mq+32i)
__device__ __forceinline__ void stsA4(float (*As)[132], int kS, int mq, const float4* ra) {
    #pragma unroll
    for (int i = 0; i < 4; i++)
        *(float4*)&As[kS][mq + i * 32] = ra[i];
}

// coalesced-gtile store: thread holds (m = mA + h*32, k = kqA..kqA+3)
__device__ __forceinline__ void stsAg(float (*As)[132], int kqA, int mA, const float4* ra) {
    #pragma unroll
    for (int h = 0; h < 4; h++) {
        int m = mA + h * 32;
        As[kqA + 0][m] = ra[h].x;
        As[kqA + 1][m] = ra[h].y;
        As[kqA + 2][m] = ra[h].z;
        As[kqA + 3][m] = ra[h].w;
    }
}

// ---------------- generic 128x64 tile GEMM (row-major A, coalesced loads) ----------------
__device__ void gtile(float (*As)[132], float (*Bs)[68],
                      const float* __restrict__ A, int lda,
                      const float* __restrict__ B, int ldb,
                      float* __restrict__ C, int ldc,
                      const float* __restrict__ Add, int ldAdd, int K) {
    int t = threadIdx.x;
    int tx8 = (t & 7) * 8, ty8 = (t >> 3) * 8;
    int mA = t >> 2, kqA = (t & 3) * 4;
    const float* Abase = A + (long)mA * lda + kqA;
    int kbB = t >> 3, c8B = (t & 7) * 8;
    const float* Bb = B + (long)kbB * ldb + c8B;

    ull acc[8][4];
    #pragma unroll
    for (int i = 0; i < 8; i++)
        #pragma unroll
        for (int jj = 0; jj < 4; jj++) acc[i][jj] = 0ull;

    float4 ra[4], rb0, rb1;
    #pragma unroll
    for (int h = 0; h < 4; h++) ra[h] = __ldcg((const float4*)(Abase + (long)h * 32 * lda));
    rb0 = __ldcg((const float4*)Bb);
    rb1 = __ldcg((const float4*)(Bb + 4));
    stsAg(As, kqA, mA, ra);
    *(float4*)&Bs[kbB][c8B] = rb0;
    *(float4*)&Bs[kbB][c8B + 4] = rb1;
    __syncthreads();

    int KT = K >> 4;
    for (int kt = 0; kt < KT; kt++) {
        int cur = kt & 1;
        bool more = (kt + 1 < KT);
        if (more) {
            int k0 = (kt + 1) * 16;
            #pragma unroll
            for (int h = 0; h < 4; h++)
                ra[h] = __ldcg((const float4*)(Abase + k0 + (long)h * 32 * lda));
            rb0 = __ldcg((const float4*)(Bb + (long)k0 * ldb));
            rb1 = __ldcg((const float4*)(Bb + (long)k0 * ldb + 4));
        }
        core16p(As + cur * 16, Bs + cur * 16, ty8, tx8, acc);
        if (more) {
            stsAg(As + (cur ^ 1) * 16, kqA, mA, ra);
            *(float4*)&Bs[(cur ^ 1) * 16 + kbB][c8B] = rb0;
            *(float4*)&Bs[(cur ^ 1) * 16 + kbB][c8B + 4] = rb1;
        }
        __syncthreads();
    }

    #pragma unroll
    for (int e = 0; e < 8; e++) {
        float2 x0 = up2(acc[e][0]), x1 = up2(acc[e][1]);
        float2 x2 = up2(acc[e][2]), x3 = up2(acc[e][3]);
        float4 v0 = make_float4(x0.x, x0.y, x1.x, x1.y);
        float4 v1 = make_float4(x2.x, x2.y, x3.x, x3.y);
        long off = (long)(ty8 + e) * ldc + tx8;
        if (Add != nullptr) {
            const float* ap = Add + (long)(ty8 + e) * ldAdd + tx8;
            float4 a0 = __ldcg((const float4*)ap);
            float4 a1 = __ldcg((const float4*)(ap + 4));
            v0.x += a0.x; v0.y += a0.y; v0.z += a0.z; v0.w += a0.w;
            v1.x += a1.x; v1.y += a1.y; v1.z += a1.z; v1.w += a1.w;
        }
        float* cp = C + off;
        *(float4*)cp = v0;
        *(float4*)(cp + 4) = v1;
    }
}

// ---------------- s32 tile (A from UT, k-major coalesced) ----------------
__device__ void s32_tile(int q, int col0, float (*As)[132], float (*Bs)[68]) {
    int t = threadIdx.x;
    int tx8 = (t & 7) * 8, ty8 = (t >> 3) * 8;
    int kS = t >> 3, mq = (t & 7) * 4;
    const float* uBase = d_UT + (long)q * (LCH * NU * BB);
    int kbB = t >> 3, c8B = (t & 7) * 8;

    ull acc[8][4];
    #pragma unroll
    for (int i = 0; i < 8; i++)
        #pragma unroll
        for (int jj = 0; jj < 4; jj++) acc[i][jj] = 0ull;

    float4 ra[4], rb0, rb1;
    {
        const float* src = uBase + (long)kS * BB + mq;
        #pragma unroll
        for (int i = 0; i < 4; i++) ra[i] = __ldcg((const float4*)(src + i * 32));
        const float* brow = d_Gp + (long)((31 - (kbB >> 5)) * NU + (kbB & 31)) * NH + col0 + c8B;
        rb0 = __ldcg((const float4*)brow);
        rb1 = __ldcg((const float4*)(brow + 4));
    }
    stsA4(As, kS, mq, ra);
    *(float4*)&Bs[kbB][c8B] = rb0;
    *(float4*)&Bs[kbB][c8B + 4] = rb1;
    __syncthreads();

    const int KT = (LCH * NU) >> 4;  // 64
    for (int kt = 0; kt < KT; kt++) {
        int cur = kt & 1;
        bool more = (kt + 1 < KT);
        if (more) {
            int k0 = (kt + 1) * 16;
            const float* src = uBase + (long)(k0 + kS) * BB + mq;
            #pragma unroll
            for (int i = 0; i < 4; i++) ra[i] = __ldcg((const float4*)(src + i * 32));
            int kb = k0 + kbB;
            const float* brow = d_Gp + (long)((31 - (kb >> 5)) * NU + (kb & 31)) * NH + col0 + c8B;
            rb0 = __ldcg((const float4*)brow);
            rb1 = __ldcg((const float4*)(brow + 4));
        }
        core16p(As + cur * 16, Bs + cur * 16, ty8, tx8, acc);
        if (more) {
            stsA4(As + (cur ^ 1) * 16, kS, mq, ra);
            *(float4*)&Bs[(cur ^ 1) * 16 + kbB][c8B] = rb0;
            *(float4*)&Bs[(cur ^ 1) * 16 + kbB][c8B + 4] = rb1;
        }
        __syncthreads();
    }

    float4 bl0 = __ldcg((const float4*)&d_Sv[32 * NH + col0 + tx8]);
    float4 bl1 = __ldcg((const float4*)&d_Sv[32 * NH + col0 + tx8 + 4]);
    #pragma unroll
    for (int e = 0; e < 8; e++) {
        int r = ty8 + e;
        float2 x0 = up2(acc[e][0]), x1 = up2(acc[e][1]);
        float2 x2 = up2(acc[e][2]), x3 = up2(acc[e][3]);
        float4 v0 = make_float4(x0.x + bl0.x, x0.y + bl0.y, x1.x + bl0.z, x1.y + bl0.w);
        float4 v1 = make_float4(x2.x + bl1.x, x2.y + bl1.y, x3.x + bl1.z, x3.y + bl1.w);
        float* cp = d_S32 + (long)q * CH + (long)r * NH + col0 + tx8;
        *(float4*)cp = v0;
        *(float4*)(cp + 4) = v1;
    }
}

// ---------------- seq tile: D[32x64 tile] = X @ W + Sp ----------------
__device__ void seq_tile(const float* __restrict__ X, const float* __restrict__ W,
                         const float* __restrict__ Sp, float* __restrict__ D,
                         int row0, int col0, void* sraw) {
    float (*Asq)[36] = (float(*)[36])sraw;
    float (*Bsq)[68] = (float(*)[68])((char*)sraw + 32 * 36 * sizeof(float));
    int t = threadIdx.x;
    int tx8 = (t & 7) * 8;
    int ty2 = (t >> 3) * 2;
    int rA = t >> 2, kqA = (t & 3) * 4;
    int kbB = t >> 3, c8B = (t & 7) * 8;
    const float* Bbase = W + (long)kbB * NH + col0 + c8B;
    const float* Axrow = X + (long)(row0 + rA) * NH;

    ull acc[2][4];
    #pragma unroll
    for (int i = 0; i < 2; i++)
        #pragma unroll
        for (int jj = 0; jj < 4; jj++) acc[i][jj] = 0ull;

    float4 ra, rb0, rb1;
    ra = __ldcg((const float4*)(Axrow + kqA));
    rb0 = __ldcg((const float4*)Bbase);
    rb1 = __ldcg((const float4*)(Bbase + 4));
    Asq[kqA + 0][rA] = ra.x; Asq[kqA + 1][rA] = ra.y;
    Asq[kqA + 2][rA] = ra.z; Asq[kqA + 3][rA] = ra.w;
    *(float4*)&Bsq[kbB][c8B] = rb0;
    *(float4*)&Bsq[kbB][c8B + 4] = rb1;
    __syncthreads();

    const int KT = NH >> 4;  // 32
    for (int kt = 0; kt < KT; kt++) {
        int cur = kt & 1;
        bool more = (kt + 1 < KT);
        if (more) {
            int k0 = (kt + 1) * 16;
            ra = __ldcg((const float4*)(Axrow + k0 + kqA));
            rb0 = __ldcg((const float4*)(Bbase + (long)k0 * NH));
            rb1 = __ldcg((const float4*)(Bbase + (long)k0 * NH + 4));
        }
        #pragma unroll
        for (int k = 0; k < 16; k++) {
            float2 a = *(const float2*)&Asq[cur * 16 + k][ty2];
            ulonglong2 b0 = *(const ulonglong2*)&Bsq[cur * 16 + k][tx8];
            ulonglong2 b1 = *(const ulonglong2*)&Bsq[cur * 16 + k][tx8 + 4];
            ull p0 = pk2(a.x), p1 = pk2(a.y);
            fma2(acc[0][0], p0, b0.x); fma2(acc[0][1], p0, b0.y);
            fma2(acc[0][2], p0, b1.x); fma2(acc[0][3], p0, b1.y);
            fma2(acc[1][0], p1, b0.x); fma2(acc[1][1], p1, b0.y);
            fma2(acc[1][2], p1, b1.x); fma2(acc[1][3], p1, b1.y);
        }
        if (more) {
            int nb = (cur ^ 1) * 16;
            Asq[nb + kqA + 0][rA] = ra.x; Asq[nb + kqA + 1][rA] = ra.y;
            Asq[nb + kqA + 2][rA] = ra.z; Asq[nb + kqA + 3][rA] = ra.w;
            *(float4*)&Bsq[nb + kbB][c8B] = rb0;
            *(float4*)&Bsq[nb + kbB][c8B + 4] = rb1;
        }
        __syncthreads();
    }

    #pragma unroll
    for (int e = 0; e < 2; e++) {
        int r = row0 + ty2 + e;
        float2 x0 = up2(acc[e][0]), x1 = up2(acc[e][1]);
        float2 x2 = up2(acc[e][2]), x3 = up2(acc[e][3]);
        const float* ap = Sp + (long)r * NH + col0 + tx8;
        float4 a0 = __ldcg((const float4*)ap);
        float4 a1 = __ldcg((const float4*)(ap + 4));
        float4 v0 = make_float4(x0.x + a0.x, x0.y + a0.y, x1.x + a0.z, x1.y + a0.w);
        float4 v1 = make_float4(x2.x + a1.x, x2.y + a1.y, x3.x + a1.z, x3.y + a1.w);
        float* dp = D + (long)r * NH + col0 + tx8;
        *(float4*)dp = v0;
        *(float4*)(dp + 4) = v1;
    }
}

// ---------------- grid barrier ----------------
__device__ __forceinline__ void gbar(unsigned& target) {
    __syncthreads();
    __threadfence();
    target += NB;
    if (threadIdx.x == 0) {
        atomicAdd(&d_bar, 1u);
        while (atomicAdd(&d_bar, 0u) < target) {}
    }
    __syncthreads();
}

// ---------------- MEGA kernel ----------------
__global__ void __launch_bounds__(128, 2) mega_kernel(const float* __restrict__ x2y_b) {
    __shared__ float As[32][132];
    __shared__ float Bs[32][68];
    int bid = blockIdx.x;
    unsigned target = 0;

    // phases 0-4: powers A^2..A^32, Cbuf/Gp doubling, bias-row doubling
    for (int lvl = 1; lvl <= 5; lvl++) {
        const float* Mp = (lvl == 1) ? d_A : d_Pow[lvl - 2];
        int colTiles = 1 << (lvl - 1);
        int cb = 4 * colTiles;
        int gpRT = (32 << (lvl - 1)) / 128; if (gpRT < 1) gpRT = 1;
        int gp = 8 * gpRT;
        int total = 32 + cb + gp + 8;
        for (int tl = bid; tl < total; tl += NB) {
            if (tl < 32) {
                int row0 = (tl >> 3) * 128, col0 = (tl & 7) * 64;
                gtile(As, Bs, Mp + (long)row0 * NH, NH, Mp + col0, NH,
                      d_Pow[lvl - 1] + (long)row0 * NH + col0, NH, nullptr, 0, NH);
            } else if (tl < 32 + cb) {
                int b = tl - 32;
                int rowTile = b / colTiles, colTile = b % colTiles;
                int row0 = rowTile * 128;
                gtile(As, Bs, Mp + (long)row0 * NH, NH,
                      d_Cbuf + colTile * 64, LDCB,
                      d_Cbuf + (long)row0 * LDCB + (64 << (lvl - 1)) + colTile * 64, LDCB,
                      nullptr, 0, NH);
            } else if (tl < 32 + cb + gp) {
                int b = tl - 32 - cb;
                int rowTile = b >> 3, colTile = b & 7;
                int row0in = rowTile * 128;
                int shift = 32 << (lvl - 1);
                gtile(As, Bs, d_Gp + (long)row0in * NH, NH, Mp + colTile * 64, NH,
                      d_Gp + (long)(row0in + shift) * NH + colTile * 64, NH, nullptr, 0, NH);
            } else {
                int col = tl - 32 - cb - gp;
                int m = 1 << (lvl - 1);
                gtile(As, Bs, d_Sv + NH, NH, Mp + col * 64, NH,
                      d_Sv + (long)(m + 1) * NH + col * 64, NH,
                      d_Sv + (long)m * NH + col * 64, 0, NH);
            }
        }
        gbar(target);
    }

    // phase 5: A^64 squaring (32) + Hd (8) + yb (1) + s32 (512)
    {
        const float* Mp = d_Pow[4];
        for (int tl = bid; tl < 553; tl += NB) {
            if (tl < 32) {
                int row0 = (tl >> 3) * 128, col0 = (tl & 7) * 64;
                gtile(As, Bs, Mp + (long)row0 * NH, NH, Mp + col0, NH,
                      d_Pow[5] + (long)row0 * NH + col0, NH, nullptr, 0, NH);
            } else if (tl < 40) {
                int rowTile = tl - 32;
                gtile(As, Bs, d_Gp + (long)rowTile * 128 * NH, NH, d_Cbuf, LDCB,
                      d_Hd + (long)rowTile * 128 * NY, NY, nullptr, 0, NH);
            } else if (tl < 41) {
                gtile(As, Bs, d_Sv, NH, d_Cbuf, LDCB, d_yb, NY, x2y_b, 0, NH);
            } else {
                int b = tl - 41;
                s32_tile(b >> 3, (b & 7) * 64, As, Bs);
            }
        }
        gbar(target);
    }

    // phase 6: A^128 squaring + combine1 (S64)
    {
        const float* Mp = d_Pow[5];
        for (int tl = bid; tl < 32 + 256; tl += NB) {
            if (tl < 32) {
                int row0 = (tl >> 3) * 128, col0 = (tl & 7) * 64;
                gtile(As, Bs, Mp + (long)row0 * NH, NH, Mp + col0, NH,
                      d_Pow[6] + (long)row0 * NH + col0, NH, nullptr, 0, NH);
            } else {
                int b = tl - 32;
                int q = b >> 3, col0 = (b & 7) * 64;
                gtile(As, Bs, d_S32 + 2L * q * CH, NH, d_Pow[4] + col0, NH,
                      d_S64 + (long)q * CH + col0, NH,
                      d_S32 + (2L * q + 1) * CH + col0, NH, NH);
            }
        }
        gbar(target);
    }
    // phase 7: A^256 squaring + combine2 (S128)
    {
        const float* Mp = d_Pow[6];
        for (int tl = bid; tl < 32 + 128; tl += NB) {
            if (tl < 32) {
                int row0 = (tl >> 3) * 128, col0 = (tl & 7) * 64;
                gtile(As, Bs, Mp + (long)row0 * NH, NH, Mp + col0, NH,
                      d_Pow[7] + (long)row0 * NH + col0, NH, nullptr, 0, NH);
            } else {
                int b = tl - 32;
                int q = b >> 3, col0 = (b & 7) * 64;
                gtile(As, Bs, d_S64 + 2L * q * CH, NH, d_Pow[5] + col0, NH,
                      d_S128 + (long)q * CH + col0, NH,
                      d_S64 + (2L * q + 1) * CH + col0, NH, NH);
            }
        }
        gbar(target);
    }
    // phase 8: combine3 (S256)
    {
        for (int tl = bid; tl < 64; tl += NB) {
            int q = tl >> 3, col0 = (tl & 7) * 64;
            gtile(As, Bs, d_S128 + 2L * q * CH, NH, d_Pow[6] + col0, NH,
                  d_S256 + (long)q * CH + col0, NH,
                  d_S128 + (2L * q + 1) * CH + col0, NH, NH);
        }
        gbar(target);
    }
    // phases 9-16: sequential chain, 8 steps of A^256
    for (int s = 0; s < 8; s++) {
        for (int tl = bid; tl < 32; tl += NB) {
            int row0 = (tl >> 3) * 32, col0 = (tl & 7) * 64;
            seq_tile(d_Xc + 8L * s * CH, d_Pow[7], d_S256 + (long)s * CH,
                     d_Xc + 8L * (s + 1) * CH, row0, col0, (void*)As);
        }
        gbar(target);
    }
    // phase 17: fill Xc[8r+4]
    {
        for (int tl = bid; tl < 64; tl += NB) {
            int r = tl >> 3, col0 = (tl & 7) * 64;
            gtile(As, Bs, d_Xc + 8L * r * CH, NH, d_Pow[6] + col0, NH,
                  d_Xc + (8L * r + 4) * CH + col0, NH,
                  d_S128 + 2L * r * CH + col0, NH, NH);
        }
        gbar(target);
    }
    // phase 18: fill Xc[4m+2]
    {
        for (int tl = bid; tl < 128; tl += NB) {
            int m = tl >> 3, col0 = (tl & 7) * 64;
            gtile(As, Bs, d_Xc + 4L * m * CH, NH, d_Pow[5] + col0, NH,
                  d_Xc + (4L * m + 2) * CH + col0, NH,
                  d_S64 + 2L * m * CH + col0, NH, NH);
        }
        gbar(target);
    }
    // phase 19: fill Xc[2n+1]
    {
        for (int tl = bid; tl < 256; tl += NB) {
            int n = tl >> 3, col0 = (tl & 7) * 64;
            gtile(As, Bs, d_Xc + 2L * n * CH, NH, d_Pow[4] + col0, NH,
                  d_Xc + (2L * n + 1) * CH + col0, NH,
                  d_S32 + 2L * n * CH + col0, NH, NH);
        }
        gbar(target);
    }
    // phase 20: transpose all 65 states Xc -> XcT
    {
        float (*tt)[33] = (float(*)[33])((void*)As);
        int t = threadIdx.x;
        int tx = t & 31, tyy = t >> 5;  // 32 x 4
        for (int tl = bid; tl < 65 * 64; tl += NB) {
            int s = tl >> 6;
            int rem = tl & 63;
            int kt0 = (rem >> 2) * 32, mt0 = (rem & 3) * 32;
            const float* src = d_Xc + (long)s * CH;
            float* dst = d_XcT + (long)s * CH;
            __syncthreads();
            #pragma unroll
            for (int r = 0; r < 8; r++) {
                int m = mt0 + tyy * 8 + r;
                tt[tyy * 8 + r][tx] = __ldcg(src + (long)m * NH + kt0 + tx);
            }
            __syncthreads();
            #pragma unroll
            for (int r = 0; r < 8; r++) {
                int k = kt0 + tyy * 8 + r;
                dst[(long)k * BB + mt0 + tx] = tt[tx][tyy * 8 + r];
            }
        }
    }
}

// ---------------- transpose A + transpose U ----------------
__global__ void transAU_kernel(const float* __restrict__ xu2x_w,
                               const float* __restrict__ U) {
    int b = blockIdx.x;
    int t = threadIdx.x;
    if (b < 256) {
        __shared__ float tile[32][33];
        int bx = (b & 15) * 32, by = (b >> 4) * 32;
        int tx = t & 31, ty = t >> 5;  // 32 x 8
        #pragma unroll
        for (int r = 0; r < 4; r++)
            tile[ty + r * 8][tx] = xu2x_w[(long)(by + ty + r * 8) * KIN + bx + tx];
        __syncthreads();
        #pragma unroll
        for (int r = 0; r < 4; r++)
            d_A[(long)(bx + ty + r * 8) * NH + by + tx] = tile[tx][ty + r * 8];
    } else {
        __shared__ float tile[128][33];
        int slice = b - 256;  // 0..2047
        const float* src = U + (long)slice * (BB * NU);
        float* dst = d_UT + (long)slice * (NU * BB);
        int u = t & 31, brow = t >> 5;  // 32 x 8
        #pragma unroll
        for (int r = 0; r < 16; r++)
            tile[brow + r * 8][u] = src[(long)(brow + r * 8) * NU + u];
        __syncthreads();
        int uo = t >> 3, mb = (t & 7) * 16;
        #pragma unroll
        for (int c = 0; c < 16; c++)
            dst[(long)uo * BB + mb + c] = tile[mb + c][uo];
    }
}

// ---------------- prep2: Gp0, C0, x0, Sv init, barrier reset ----------------
__global__ void prep2_kernel(const float* __restrict__ y0,
                             const float* __restrict__ y2x_w,
                             const float* __restrict__ y2x_b,
                             const float* __restrict__ xu2x_w,
                             const float* __restrict__ xu2x_b,
                             const float* __restrict__ x2y_w) {
    int idx = blockIdx.x * blockDim.x + threadIdx.x;
    int stride = gridDim.x * blockDim.x;
    if (idx == 0) d_bar = 0u;
    for (int t = idx; t < NU * NH; t += stride) {
        int u = t / NH, h = t % NH;
        d_Gp[u * NH + h] = xu2x_w[h * KIN + NH + u];
    }
    for (int t = idx; t < NH * NY; t += stride) {
        int h = t / NY, n = t % NY;
        d_Cbuf[h * LDCB + n] = x2y_w[n * NH + h];
    }
    for (int t = idx; t < 192 * NH; t += stride) {
        float v = 0.0f;
        if (t >= NH && t < 2 * NH) v = xu2x_b[t - NH];
        d_Sv[t] = v;
    }
    for (int t = idx; t < BB * NH; t += stride) {
        int b = t / NH, h = t % NH;
        float acc = y2x_b[h];
        #pragma unroll 8
        for (int n = 0; n < NY; n++) acc += y0[b * NY + n] * y2x_w[h * NY + n];
        d_Xc[b * NH + h] = acc;
    }
}

// ---------------- output pass (k-major A from XcT/UT) ----------------
__global__ void __launch_bounds__(128, 3) out_kernel(float* __restrict__ out) {
    __shared__ float As[32][132];
    __shared__ float Bs[32][68];
    int bx = blockIdx.x;
    int p, j;
    if (bx == PCH * LCH) { p = PCH; j = 0; }
    else { j = 31 - (bx >> 6); p = bx & 63; }
    int pjOut = p * LCH + j;
    int t = threadIdx.x;
    int KT = 32 + 2 * j;
    int tx8 = (t & 7) * 8, ty8 = (t >> 3) * 8;

    int kS = t >> 3, mq = (t & 7) * 4;
    const float* xT = d_XcT + (long)p * CH;
    const float* uT = d_UT + (long)p * (LCH * NU * BB);
    int kbB = t >> 3, c8B = (t & 7) * 8;

    ull acc[8][4];
    #pragma unroll
    for (int i = 0; i < 8; i++)
        #pragma unroll
        for (int jj = 0; jj < 4; jj++) acc[i][jj] = 0ull;

    float4 ra[4], rb0, rb1;
    {
        const float* src = xT + (long)kS * BB + mq;
        #pragma unroll
        for (int i = 0; i < 4; i++) ra[i] = __ldcg((const float4*)(src + i * 32));
        const float* brow = d_Cbuf + (long)kbB * LDCB + j * NY + c8B;
        rb0 = *(const float4*)brow;
        rb1 = *(const float4*)(brow + 4);
    }
    stsA4(As, kS, mq, ra);
    *(float4*)&Bs[kbB][c8B] = rb0;
    *(float4*)&Bs[kbB][c8B + 4] = rb1;
    __syncthreads();

    for (int kt = 0; kt < KT; kt++) {
        int cur = kt & 1;
        bool more = (kt + 1 < KT);
        if (more) {
            int k0 = (kt + 1) * 16;
            const float* src = (k0 < NH)
                ? xT + (long)(k0 + kS) * BB + mq
                : uT + (long)(k0 - NH + kS) * BB + mq;
            #pragma unroll
            for (int i = 0; i < 4; i++) ra[i] = __ldcg((const float4*)(src + i * 32));
            int kb = k0 + kbB;
            const float* brow;
            if (kb < NH) {
                brow = d_Cbuf + (long)kb * LDCB + j * NY + c8B;
            } else {
                int kc = kb - NH;
                brow = d_Hd + (long)((j - 1 - (kc >> 5)) * NU + (kc & 31)) * NY + c8B;
            }
            rb0 = *(const float4*)brow;
            rb1 = *(const float4*)(brow + 4);
        }
        core16p(As + cur * 16, Bs + cur * 16, ty8, tx8, acc);
        if (more) {
            stsA4(As + (cur ^ 1) * 16, kS, mq, ra);
            *(float4*)&Bs[(cur ^ 1) * 16 + kbB][c8B] = rb0;
            *(float4*)&Bs[(cur ^ 1) * 16 + kbB][c8B + 4] = rb1;
        }
        __syncthreads();
    }

    float4 yb0 = *(const float4*)(d_yb + j * NY + tx8);
    float4 yb1 = *(const float4*)(d_yb + j * NY + tx8 + 4);
    float* obase = out + (long)pjOut * (BB * NY);
    #pragma unroll
    for (int e = 0; e < 8; e++) {
        int r = ty8 + e;
        float2 x0 = up2(acc[e][0]), x1 = up2(acc[e][1]);
        float2 x2 = up2(acc[e][2]), x3 = up2(acc[e][3]);
        float4 v0 = make_float4(x0.x + yb0.x, x0.y + yb0.y, x1.x + yb0.z, x1.y + yb0.w);
        float4 v1 = make_float4(x2.x + yb1.x, x2.y + yb1.y, x3.x + yb1.z, x3.y + yb1.w);
        float* op = obase + (long)r * NY + tx8;
        *(float4*)op = v0;
        *(float4*)(op + 4) = v1;
    }
}

__global__ void noop_kernel() {}

// ---------------- host ----------------
extern "C" void kernel_launch(void* const* d_in, const int* in_sizes, int n_in,
                              void* d_out, int out_size) {
    const float* y0     = (const float*)d_in[0];
    const float* U      = (const float*)d_in[1];
    const float* y2x_w  = (const float*)d_in[2];
    const float* y2x_b  = (const float*)d_in[3];
    const float* xu2x_w = (const float*)d_in[4];
    const float* xu2x_b = (const float*)d_in[5];
    const float* x2y_w  = (const float*)d_in[6];
    const float* x2y_b  = (const float*)d_in[7];
    float* out = (float*)d_out;

    // ncu captures overall launch #5 = our 4th -> profile MEGA this round.
    transAU_kernel<<<256 + 2048, 256>>>(xu2x_w, U);                        // ours 1
    prep2_kernel<<<128, 256>>>(y0, y2x_w, y2x_b, xu2x_w, xu2x_b, x2y_w);   // ours 2
    noop_kernel<<<1, 32>>>();                                              // ours 3
    mega_kernel<<<NB, 128>>>(x2y_b);                                       // ours 4 <- profiled
    out_kernel<<<PCH * LCH + 1, 128>>>(out);                               // ours 5
    (void)in_sizes; (void)n_in; (void)out_size;
}